// round 1
// baseline (speedup 1.0000x reference)
#include <cuda_runtime.h>
#include <math.h>

#define LRD   512
#define HRD   2048
#define HEADS 4
#define CH    512
#define NND   4096
#define EPSG  1e-5f

// ---------------- scratch (__device__ globals: allocation-free) ----------------
__device__ float g_Q [NND * HRD];            // 32 MB
__device__ float g_K [NND * HRD];            // 32 MB
__device__ float g_V [NND * HRD];            // 32 MB
__device__ float g_SK[NND * HRD];            // 32 MB  (skip projection)
__device__ float g_S [(size_t)HEADS * NND * NND];  // 256 MB (scores/probs)
__device__ float g_O [NND * HRD];            // 32 MB  (attn out + skip)
__device__ float g_psum[32 * HRD];
__device__ float g_psq [32 * HRD];
__device__ float g_sum[HRD];
__device__ float g_a  [HRD];
__device__ float g_c  [HRD];

// ---------------- 1) fused QKV+skip projection: out = lr_x^T @ W + b ----------
// lr_x is [LR, N] row-major, so A[n][l] = lr_x[l*N + n] (coalesced in n).
__global__ void proj_kernel(const float* __restrict__ lrx,
                            const float* __restrict__ Wq, const float* __restrict__ bq,
                            const float* __restrict__ Wk, const float* __restrict__ bk,
                            const float* __restrict__ Wv, const float* __restrict__ bv,
                            const float* __restrict__ Ws, const float* __restrict__ bs)
{
    const float* W; const float* bias; float* out;
    if      (blockIdx.z == 0) { W = Wq; bias = bq; out = g_Q;  }
    else if (blockIdx.z == 1) { W = Wk; bias = bk; out = g_K;  }
    else if (blockIdx.z == 2) { W = Wv; bias = bv; out = g_V;  }
    else                      { W = Ws; bias = bs; out = g_SK; }

    __shared__ float As[16][64];
    __shared__ float Bs[16][64];

    const int tid = threadIdx.x;
    const int tx = tid & 15, ty = tid >> 4;
    const int n0 = blockIdx.y * 64, j0 = blockIdx.x * 64;

    float acc[4][4];
#pragma unroll
    for (int i = 0; i < 4; i++)
#pragma unroll
        for (int j = 0; j < 4; j++) acc[i][j] = 0.f;

    for (int l0 = 0; l0 < LRD; l0 += 16) {
#pragma unroll
        for (int t = tid; t < 1024; t += 256) {
            int kk = t >> 6, mm = t & 63;
            As[kk][mm] = lrx[(l0 + kk) * NND + n0 + mm];
            Bs[kk][mm] = W  [(l0 + kk) * HRD + j0 + mm];
        }
        __syncthreads();
#pragma unroll
        for (int kk = 0; kk < 16; kk++) {
            float a[4], b[4];
#pragma unroll
            for (int i = 0; i < 4; i++) a[i] = As[kk][ty * 4 + i];
#pragma unroll
            for (int j = 0; j < 4; j++) b[j] = Bs[kk][tx * 4 + j];
#pragma unroll
            for (int i = 0; i < 4; i++)
#pragma unroll
                for (int j = 0; j < 4; j++) acc[i][j] = fmaf(a[i], b[j], acc[i][j]);
        }
        __syncthreads();
    }
#pragma unroll
    for (int i = 0; i < 4; i++)
#pragma unroll
        for (int j = 0; j < 4; j++)
            out[(n0 + ty * 4 + i) * HRD + j0 + tx * 4 + j] =
                acc[i][j] + bias[j0 + tx * 4 + j];
}

// ---------------- 2) scores: S_h = (Q_h @ K_h^T) / sqrt(C) --------------------
__global__ void scores_kernel()
{
    const int h  = blockIdx.z;
    const float* Q = g_Q + h * CH;
    const float* K = g_K + h * CH;
    float* S = g_S + (size_t)h * NND * NND;

    __shared__ float As[16][65];   // padded: writes stride along kk
    __shared__ float Bs[16][65];

    const int tid = threadIdx.x;
    const int tx = tid & 15, ty = tid >> 4;
    const int n0 = blockIdx.y * 64, m0 = blockIdx.x * 64;

    float acc[4][4];
#pragma unroll
    for (int i = 0; i < 4; i++)
#pragma unroll
        for (int j = 0; j < 4; j++) acc[i][j] = 0.f;

    for (int c0 = 0; c0 < CH; c0 += 16) {
#pragma unroll
        for (int t = tid; t < 1024; t += 256) {
            int r = t >> 4, kk = t & 15;
            As[kk][r] = Q[(n0 + r) * HRD + c0 + kk];
            Bs[kk][r] = K[(m0 + r) * HRD + c0 + kk];
        }
        __syncthreads();
#pragma unroll
        for (int kk = 0; kk < 16; kk++) {
            float a[4], b[4];
#pragma unroll
            for (int i = 0; i < 4; i++) a[i] = As[kk][ty * 4 + i];
#pragma unroll
            for (int j = 0; j < 4; j++) b[j] = Bs[kk][tx * 4 + j];
#pragma unroll
            for (int i = 0; i < 4; i++)
#pragma unroll
                for (int j = 0; j < 4; j++) acc[i][j] = fmaf(a[i], b[j], acc[i][j]);
        }
        __syncthreads();
    }
    const float scale = rsqrtf((float)CH);
#pragma unroll
    for (int i = 0; i < 4; i++)
#pragma unroll
        for (int j = 0; j < 4; j++)
            S[(size_t)(n0 + ty * 4 + i) * NND + m0 + tx * 4 + j] = acc[i][j] * scale;
}

// ---------------- 3) softmax over source axis (in place) ----------------------
__global__ void softmax_kernel()
{
    float* p = g_S + (size_t)blockIdx.x * NND;
    const int tid = threadIdx.x;

    float v[16];
    float mx = -INFINITY;
#pragma unroll
    for (int i = 0; i < 16; i++) { v[i] = p[tid + i * 256]; mx = fmaxf(mx, v[i]); }

    __shared__ float red[256];
    red[tid] = mx; __syncthreads();
    for (int s = 128; s > 0; s >>= 1) {
        if (tid < s) red[tid] = fmaxf(red[tid], red[tid + s]);
        __syncthreads();
    }
    mx = red[0]; __syncthreads();

    float sum = 0.f;
#pragma unroll
    for (int i = 0; i < 16; i++) { v[i] = __expf(v[i] - mx); sum += v[i]; }

    red[tid] = sum; __syncthreads();
    for (int s = 128; s > 0; s >>= 1) {
        if (tid < s) red[tid] += red[tid + s];
        __syncthreads();
    }
    const float inv = 1.0f / red[0];
#pragma unroll
    for (int i = 0; i < 16; i++) p[tid + i * 256] = v[i] * inv;
}

// ---------------- 4) out = P @ V + skip ---------------------------------------
__global__ void pv_kernel()
{
    const int h = blockIdx.z;
    const float* P = g_S + (size_t)h * NND * NND;
    const float* V = g_V + h * CH;

    __shared__ float As[16][65];
    __shared__ float Bs[16][64];

    const int tid = threadIdx.x;
    const int tx = tid & 15, ty = tid >> 4;
    const int n0 = blockIdx.y * 64, c0 = blockIdx.x * 64;

    float acc[4][4];
#pragma unroll
    for (int i = 0; i < 4; i++)
#pragma unroll
        for (int j = 0; j < 4; j++) acc[i][j] = 0.f;

    for (int m0 = 0; m0 < NND; m0 += 16) {
#pragma unroll
        for (int t = tid; t < 1024; t += 256) {
            int r = t >> 4, kk = t & 15;
            As[kk][r] = P[(size_t)(n0 + r) * NND + m0 + kk];
        }
#pragma unroll
        for (int t = tid; t < 1024; t += 256) {
            int kk = t >> 6, cc = t & 63;
            Bs[kk][cc] = V[(m0 + kk) * HRD + c0 + cc];
        }
        __syncthreads();
#pragma unroll
        for (int kk = 0; kk < 16; kk++) {
            float a[4], b[4];
#pragma unroll
            for (int i = 0; i < 4; i++) a[i] = As[kk][ty * 4 + i];
#pragma unroll
            for (int j = 0; j < 4; j++) b[j] = Bs[kk][tx * 4 + j];
#pragma unroll
            for (int i = 0; i < 4; i++)
#pragma unroll
                for (int j = 0; j < 4; j++) acc[i][j] = fmaf(a[i], b[j], acc[i][j]);
        }
        __syncthreads();
    }
#pragma unroll
    for (int i = 0; i < 4; i++)
#pragma unroll
        for (int j = 0; j < 4; j++) {
            int gi = (n0 + ty * 4 + i) * HRD + h * CH + c0 + tx * 4 + j;
            g_O[gi] = acc[i][j] + g_SK[gi];
        }
}

// ---------------- 5) per-channel stats (deterministic 2-stage) ---------------
__global__ void stats1_kernel()
{
    const int j  = blockIdx.x * 256 + threadIdx.x;
    const int r0 = blockIdx.y * 128;
    float s = 0.f, q = 0.f;
    for (int r = 0; r < 128; r++) {
        float v = g_O[(r0 + r) * HRD + j];
        s += v; q = fmaf(v, v, q);
    }
    g_psum[blockIdx.y * HRD + j] = s;
    g_psq [blockIdx.y * HRD + j] = q;
}

// GraphNorm + L2-row-norm collapse into per-channel affine: hr[j][n] = a_j*out[n][j] + c_j
__global__ void stats2_kernel(const float* __restrict__ w, const float* __restrict__ b,
                              const float* __restrict__ ms)
{
    const int j = blockIdx.x * 256 + threadIdx.x;
    float s = 0.f, q = 0.f;
    for (int i = 0; i < 32; i++) { s += g_psum[i * HRD + j]; q += g_psq[i * HRD + j]; }
    const float invN = 1.0f / (float)NND;
    const float m   = s * invN;
    const float sc  = ms[j];
    const float var = q * invN - 2.f * sc * m * m + sc * sc * m * m;
    const float rstd = rsqrtf(var + EPSG);
    const float wj = w[j], bj = b[j];
    const float sumc = s - (float)NND * sc * m;     // sum of centered values
    const float normsq = wj * wj * rstd * rstd * ((float)NND * var)
                       + 2.f * wj * bj * rstd * sumc
                       + (float)NND * bj * bj;
    const float inorm = rsqrtf(normsq);
    g_a[j]   = rstd * wj * inorm;
    g_c[j]   = (bj - sc * m * rstd * wj) * inorm;
    g_sum[j] = s;
}

// ---------------- 6) Gram out^T@out, affine+relu epilogue --------------------
__global__ void gram_kernel(float* __restrict__ out)
{
    __shared__ float As[16][64];
    __shared__ float Bs[16][64];

    const int tid = threadIdx.x;
    const int tx = tid & 15, ty = tid >> 4;
    const int i0 = blockIdx.y * 64, j0 = blockIdx.x * 64;

    float acc[4][4];
#pragma unroll
    for (int i = 0; i < 4; i++)
#pragma unroll
        for (int j = 0; j < 4; j++) acc[i][j] = 0.f;

    for (int n0 = 0; n0 < NND; n0 += 16) {
#pragma unroll
        for (int t = tid; t < 1024; t += 256) {
            int kk = t >> 6, cc = t & 63;
            As[kk][cc] = g_O[(n0 + kk) * HRD + i0 + cc];
            Bs[kk][cc] = g_O[(n0 + kk) * HRD + j0 + cc];
        }
        __syncthreads();
#pragma unroll
        for (int kk = 0; kk < 16; kk++) {
            float a[4], b[4];
#pragma unroll
            for (int i = 0; i < 4; i++) a[i] = As[kk][ty * 4 + i];
#pragma unroll
            for (int j = 0; j < 4; j++) b[j] = Bs[kk][tx * 4 + j];
#pragma unroll
            for (int i = 0; i < 4; i++)
#pragma unroll
                for (int j = 0; j < 4; j++) acc[i][j] = fmaf(a[i], b[j], acc[i][j]);
        }
        __syncthreads();
    }
#pragma unroll
    for (int ii = 0; ii < 4; ii++)
#pragma unroll
        for (int jj = 0; jj < 4; jj++) {
            int i = i0 + ty * 4 + ii, j = j0 + tx * 4 + jj;
            float g = g_a[i] * g_a[j] * acc[ii][jj]
                    + g_a[i] * g_c[j] * g_sum[i]
                    + g_c[i] * g_a[j] * g_sum[j]
                    + (float)NND * g_c[i] * g_c[j];
            out[i * HRD + j] = fmaxf(g, 0.f);
        }
}

// ---------------- launch ------------------------------------------------------
extern "C" void kernel_launch(void* const* d_in, const int* in_sizes, int n_in,
                              void* d_out, int out_size)
{
    const float* lrx = (const float*)d_in[0];
    const float* Wq  = (const float*)d_in[1];
    const float* bq  = (const float*)d_in[2];
    const float* Wk  = (const float*)d_in[3];
    const float* bk  = (const float*)d_in[4];
    const float* Wv  = (const float*)d_in[5];
    const float* bv  = (const float*)d_in[6];
    const float* Ws  = (const float*)d_in[7];
    const float* bs  = (const float*)d_in[8];
    const float* gw  = (const float*)d_in[9];
    const float* gb  = (const float*)d_in[10];
    const float* gms = (const float*)d_in[11];

    dim3 t(256);
    proj_kernel   <<<dim3(HRD / 64, NND / 64, 4), t>>>(lrx, Wq, bq, Wk, bk, Wv, bv, Ws, bs);
    scores_kernel <<<dim3(NND / 64, NND / 64, HEADS), t>>>();
    softmax_kernel<<<HEADS * NND, t>>>();
    pv_kernel     <<<dim3(CH / 64, NND / 64, HEADS), t>>>();
    stats1_kernel <<<dim3(HRD / 256, NND / 128), t>>>();
    stats2_kernel <<<HRD / 256, t>>>(gw, gb, gms);
    gram_kernel   <<<dim3(HRD / 64, HRD / 64), t>>>((float*)d_out);
}

// round 3
// speedup vs baseline: 3.5234x; 3.5234x over previous
#include <cuda_runtime.h>
#include <math.h>
#include <stdint.h>

#define LRD   512
#define HRD   2048
#define HEADS 4
#define CH    512
#define NND   4096
#define EPSG  1e-5f
#define NT    256
#define TS    36              // smem tile row stride (floats): 4*row+col banks -> conflict-free frags
#define TILEF (128 * TS)      // floats per tile buffer

// ---------------- scratch (__device__ globals: allocation-free) --------------
__device__ float g_Q [NND * HRD];
__device__ float g_K [NND * HRD];
__device__ float g_V [NND * HRD];
__device__ float g_SK[NND * HRD];
__device__ float g_S [(size_t)HEADS * NND * NND];   // 256 MB scores/probs
__device__ float g_O [NND * HRD];
__device__ float g_psum[32 * HRD];
__device__ float g_psq [32 * HRD];
__device__ float g_sum[HRD];
__device__ float g_a  [HRD];
__device__ float g_c  [HRD];

// ---------------- helpers ----------------------------------------------------
__device__ __forceinline__ uint32_t tf32r(float f) {
    uint32_t u; asm("cvt.rna.tf32.f32 %0, %1;" : "=r"(u) : "f"(f)); return u;
}

__device__ __forceinline__ void mma8(float* c, const uint32_t* a, const uint32_t* b) {
    asm volatile(
        "mma.sync.aligned.m16n8k8.row.col.f32.tf32.tf32.f32 "
        "{%0,%1,%2,%3}, {%4,%5,%6,%7}, {%8,%9}, {%0,%1,%2,%3};"
        : "+f"(c[0]), "+f"(c[1]), "+f"(c[2]), "+f"(c[3])
        : "r"(a[0]), "r"(a[1]), "r"(a[2]), "r"(a[3]), "r"(b[0]), "r"(b[1]));
}

// ---------------- tile fetch/stash -------------------------------------------
// TR=false: source row-major [tile_row][k] (row = output dim, 32 k-cols/chunk)
// TR=true : source [k][tile_row] (read coalesced along tile_row)
template<bool TR>
__device__ __forceinline__ void fetch_tile(const float* __restrict__ src, int ld,
                                           int base, int k0, int tid, float* f) {
    if (TR) {
#pragma unroll
        for (int t = 0; t < 16; t++) {
            int v = tid + t * NT;
            int j = v & 127, k = v >> 7;
            f[t] = src[(size_t)(k0 + k) * ld + base + j];
        }
    } else {
#pragma unroll
        for (int t = 0; t < 4; t++) {
            int v = tid + t * NT;
            int row = v >> 3, q = v & 7;
            float4 x = *(const float4*)(src + (size_t)(base + row) * ld + k0 + q * 4);
            f[t * 4 + 0] = x.x; f[t * 4 + 1] = x.y;
            f[t * 4 + 2] = x.z; f[t * 4 + 3] = x.w;
        }
    }
}

template<bool TR>
__device__ __forceinline__ void stash_tile(float* S, int tid, const float* f) {
    uint32_t* U = (uint32_t*)S;
    if (TR) {
#pragma unroll
        for (int t = 0; t < 16; t++) {
            int v = tid + t * NT;
            int j = v & 127, k = v >> 7;
            U[j * TS + k] = tf32r(f[t]);
        }
    } else {
#pragma unroll
        for (int t = 0; t < 4; t++) {
            int v = tid + t * NT;
            int row = v >> 3, q = v & 7;
            uint4 u = make_uint4(tf32r(f[t * 4]), tf32r(f[t * 4 + 1]),
                                 tf32r(f[t * 4 + 2]), tf32r(f[t * 4 + 3]));
            *(uint4*)&U[row * TS + q * 4] = u;
        }
    }
}

// ---------------- per-chunk MMA (K=32) ---------------------------------------
__device__ __forceinline__ void compute_chunk(const float* Sa, const float* Sb,
                                              float acc[2][8][4]) {
    const int lane = threadIdx.x & 31, wid = threadIdx.x >> 5;
    const int gp = lane >> 2, tg = lane & 3;
    const int mw = (wid & 3) * 32, nw = (wid >> 2) * 64;
    const uint32_t* A = (const uint32_t*)Sa;
    const uint32_t* B = (const uint32_t*)Sb;
#pragma unroll
    for (int ks = 0; ks < 4; ks++) {
        const int k0 = ks * 8;
        uint32_t a[2][4], b[8][2];
#pragma unroll
        for (int mf = 0; mf < 2; mf++) {
            int r = mw + mf * 16 + gp;
            a[mf][0] = A[r * TS + k0 + tg];
            a[mf][1] = A[(r + 8) * TS + k0 + tg];
            a[mf][2] = A[r * TS + k0 + tg + 4];
            a[mf][3] = A[(r + 8) * TS + k0 + tg + 4];
        }
#pragma unroll
        for (int nf = 0; nf < 8; nf++) {
            int n = nw + nf * 8 + gp;
            b[nf][0] = B[n * TS + k0 + tg];
            b[nf][1] = B[n * TS + k0 + tg + 4];
        }
#pragma unroll
        for (int mf = 0; mf < 2; mf++)
#pragma unroll
            for (int nf = 0; nf < 8; nf++) mma8(acc[mf][nf], a[mf], b[nf]);
    }
}

// ---------------- GEMM core: C128x128 += A(128xK) * B(128xK)^T ---------------
template<int NC, bool TRA, bool TRB>
__device__ __forceinline__ void gemm_core(const float* __restrict__ Ag, int lda, int abase,
                                          const float* __restrict__ Bg, int ldb, int bbase,
                                          float acc[2][8][4]) {
    extern __shared__ float4 smem4[];
    float* smem = (float*)smem4;
    float* Sa = smem;
    float* Sb = smem + 2 * TILEF;
    const int tid = threadIdx.x;

#pragma unroll
    for (int mf = 0; mf < 2; mf++)
#pragma unroll
        for (int nf = 0; nf < 8; nf++)
#pragma unroll
            for (int e = 0; e < 4; e++) acc[mf][nf][e] = 0.f;

    float fa[16], fb[16];
    fetch_tile<TRA>(Ag, lda, abase, 0, tid, fa);
    fetch_tile<TRB>(Bg, ldb, bbase, 0, tid, fb);

#pragma unroll 1
    for (int i = 0; i < NC; i++) {
        const int buf = i & 1;
        stash_tile<TRA>(Sa + buf * TILEF, tid, fa);
        stash_tile<TRB>(Sb + buf * TILEF, tid, fb);
        __syncthreads();
        if (i + 1 < NC) {
            fetch_tile<TRA>(Ag, lda, abase, (i + 1) * 32, tid, fa);
            fetch_tile<TRB>(Bg, ldb, bbase, (i + 1) * 32, tid, fb);
        }
        compute_chunk(Sa + buf * TILEF, Sb + buf * TILEF, acc);
        __syncthreads();
    }
}

// epilogue coordinate helpers (per-thread fragment positions)
#define EPI_COORDS                                         \
    const int lane = threadIdx.x & 31, wid = threadIdx.x >> 5; \
    const int gp = lane >> 2, tg = lane & 3;               \
    const int mw = (wid & 3) * 32, nw = (wid >> 2) * 64;

// ---------------- 1) projections (Q,K,V,skip) --------------------------------
__global__ void __launch_bounds__(NT) proj_tc(
    const float* __restrict__ lrx,
    const float* __restrict__ Wq, const float* __restrict__ bq,
    const float* __restrict__ Wk, const float* __restrict__ bk,
    const float* __restrict__ Wv, const float* __restrict__ bv,
    const float* __restrict__ Ws, const float* __restrict__ bs)
{
    const float* W; const float* bias; float* out;
    if      (blockIdx.z == 0) { W = Wq; bias = bq; out = g_Q;  }
    else if (blockIdx.z == 1) { W = Wk; bias = bk; out = g_K;  }
    else if (blockIdx.z == 2) { W = Wv; bias = bv; out = g_V;  }
    else                      { W = Ws; bias = bs; out = g_SK; }

    const int n0 = blockIdx.y * 128, j0 = blockIdx.x * 128;
    float acc[2][8][4];
    gemm_core<LRD / 32, true, true>(lrx, NND, n0, W, HRD, j0, acc);

    EPI_COORDS;
#pragma unroll
    for (int mf = 0; mf < 2; mf++)
#pragma unroll
        for (int nf = 0; nf < 8; nf++) {
            int r = n0 + mw + mf * 16 + gp;
            int c = j0 + nw + nf * 8 + 2 * tg;
            float b0 = bias[c], b1 = bias[c + 1];
            float2 v0 = make_float2(acc[mf][nf][0] + b0, acc[mf][nf][1] + b1);
            float2 v1 = make_float2(acc[mf][nf][2] + b0, acc[mf][nf][3] + b1);
            *(float2*)&out[(size_t)r * HRD + c]       = v0;
            *(float2*)&out[(size_t)(r + 8) * HRD + c] = v1;
        }
}

// ---------------- 2) scores: S_h = (Q_h K_h^T) / sqrt(C) ---------------------
__global__ void __launch_bounds__(NT) scores_tc()
{
    const int h = blockIdx.z;
    const float* Qp = g_Q + h * CH;
    const float* Kp = g_K + h * CH;
    float* S = g_S + (size_t)h * NND * NND;
    const int n0 = blockIdx.y * 128, m0 = blockIdx.x * 128;

    float acc[2][8][4];
    gemm_core<CH / 32, false, false>(Qp, HRD, n0, Kp, HRD, m0, acc);

    const float scale = rsqrtf((float)CH);
    EPI_COORDS;
#pragma unroll
    for (int mf = 0; mf < 2; mf++)
#pragma unroll
        for (int nf = 0; nf < 8; nf++) {
            int r = n0 + mw + mf * 16 + gp;
            int c = m0 + nw + nf * 8 + 2 * tg;
            float2 v0 = make_float2(acc[mf][nf][0] * scale, acc[mf][nf][1] * scale);
            float2 v1 = make_float2(acc[mf][nf][2] * scale, acc[mf][nf][3] * scale);
            *(float2*)&S[(size_t)r * NND + c]       = v0;
            *(float2*)&S[(size_t)(r + 8) * NND + c] = v1;
        }
}

// ---------------- 3) softmax over source axis (in place) ---------------------
__global__ void softmax_kernel()
{
    float* p = g_S + (size_t)blockIdx.x * NND;
    const int tid = threadIdx.x;

    float v[16];
    float mx = -INFINITY;
#pragma unroll
    for (int i = 0; i < 16; i++) { v[i] = p[tid + i * 256]; mx = fmaxf(mx, v[i]); }

    __shared__ float red[256];
    red[tid] = mx; __syncthreads();
    for (int s = 128; s > 0; s >>= 1) {
        if (tid < s) red[tid] = fmaxf(red[tid], red[tid + s]);
        __syncthreads();
    }
    mx = red[0]; __syncthreads();

    float sum = 0.f;
#pragma unroll
    for (int i = 0; i < 16; i++) { v[i] = __expf(v[i] - mx); sum += v[i]; }

    red[tid] = sum; __syncthreads();
    for (int s = 128; s > 0; s >>= 1) {
        if (tid < s) red[tid] += red[tid + s];
        __syncthreads();
    }
    const float inv = 1.0f / red[0];
#pragma unroll
    for (int i = 0; i < 16; i++) p[tid + i * 256] = v[i] * inv;
}

// ---------------- 4) out = P @ V + skip --------------------------------------
__global__ void __launch_bounds__(NT) pv_tc()
{
    const int h = blockIdx.z;
    const float* P = g_S + (size_t)h * NND * NND;
    const float* V = g_V + h * CH;
    const int n0 = blockIdx.y * 128, c0 = blockIdx.x * 128;

    float acc[2][8][4];
    gemm_core<NND / 32, false, true>(P, NND, n0, V, HRD, c0, acc);

    EPI_COORDS;
#pragma unroll
    for (int mf = 0; mf < 2; mf++)
#pragma unroll
        for (int nf = 0; nf < 8; nf++) {
            int r = n0 + mw + mf * 16 + gp;
            int c = h * CH + c0 + nw + nf * 8 + 2 * tg;
            size_t g0 = (size_t)r * HRD + c, g1 = (size_t)(r + 8) * HRD + c;
            float2 s0 = *(const float2*)&g_SK[g0];
            float2 s1 = *(const float2*)&g_SK[g1];
            float2 v0 = make_float2(acc[mf][nf][0] + s0.x, acc[mf][nf][1] + s0.y);
            float2 v1 = make_float2(acc[mf][nf][2] + s1.x, acc[mf][nf][3] + s1.y);
            *(float2*)&g_O[g0] = v0;
            *(float2*)&g_O[g1] = v1;
        }
}

// ---------------- 5) per-channel stats (deterministic 2-stage) ---------------
__global__ void stats1_kernel()
{
    const int j  = blockIdx.x * 256 + threadIdx.x;
    const int r0 = blockIdx.y * 128;
    float s = 0.f, q = 0.f;
    for (int r = 0; r < 128; r++) {
        float v = g_O[(size_t)(r0 + r) * HRD + j];
        s += v; q = fmaf(v, v, q);
    }
    g_psum[blockIdx.y * HRD + j] = s;
    g_psq [blockIdx.y * HRD + j] = q;
}

__global__ void stats2_kernel(const float* __restrict__ w, const float* __restrict__ b,
                              const float* __restrict__ ms)
{
    const int j = blockIdx.x * 256 + threadIdx.x;
    float s = 0.f, q = 0.f;
    for (int i = 0; i < 32; i++) { s += g_psum[i * HRD + j]; q += g_psq[i * HRD + j]; }
    const float invN = 1.0f / (float)NND;
    const float m    = s * invN;
    const float sc   = ms[j];
    const float var  = q * invN - 2.f * sc * m * m + sc * sc * m * m;
    const float rstd = rsqrtf(var + EPSG);
    const float wj = w[j], bj = b[j];
    const float sumc = s - (float)NND * sc * m;
    const float normsq = wj * wj * rstd * rstd * ((float)NND * var)
                       + 2.f * wj * bj * rstd * sumc
                       + (float)NND * bj * bj;
    const float inorm = rsqrtf(normsq);
    g_a[j]   = rstd * wj * inorm;
    g_c[j]   = (bj - sc * m * rstd * wj) * inorm;
    g_sum[j] = s;
}

// ---------------- 6) Gram O^T O with fused GraphNorm+L2 affine + relu --------
__global__ void __launch_bounds__(NT) gram_tc(float* __restrict__ out)
{
    const int i0 = blockIdx.y * 128, j0 = blockIdx.x * 128;

    float acc[2][8][4];
    gemm_core<NND / 32, true, true>(g_O, HRD, i0, g_O, HRD, j0, acc);

    EPI_COORDS;
#pragma unroll
    for (int mf = 0; mf < 2; mf++)
#pragma unroll
        for (int nf = 0; nf < 8; nf++) {
            int gi = i0 + mw + mf * 16 + gp;
            int gj = j0 + nw + nf * 8 + 2 * tg;
            float ai0 = g_a[gi],     ci0 = g_c[gi],     Si0 = g_sum[gi];
            float ai1 = g_a[gi + 8], ci1 = g_c[gi + 8], Si1 = g_sum[gi + 8];
            float aj0 = g_a[gj],     cj0 = g_c[gj],     Sj0 = g_sum[gj];
            float aj1 = g_a[gj + 1], cj1 = g_c[gj + 1], Sj1 = g_sum[gj + 1];

            float r00 = ai0 * aj0 * acc[mf][nf][0] + ai0 * cj0 * Si0 + ci0 * aj0 * Sj0 + (float)NND * ci0 * cj0;
            float r01 = ai0 * aj1 * acc[mf][nf][1] + ai0 * cj1 * Si0 + ci0 * aj1 * Sj1 + (float)NND * ci0 * cj1;
            float r10 = ai1 * aj0 * acc[mf][nf][2] + ai1 * cj0 * Si1 + ci1 * aj0 * Sj0 + (float)NND * ci1 * cj0;
            float r11 = ai1 * aj1 * acc[mf][nf][3] + ai1 * cj1 * Si1 + ci1 * aj1 * Sj1 + (float)NND * ci1 * cj1;

            float2 v0 = make_float2(fmaxf(r00, 0.f), fmaxf(r01, 0.f));
            float2 v1 = make_float2(fmaxf(r10, 0.f), fmaxf(r11, 0.f));
            *(float2*)&out[(size_t)gi * HRD + gj]       = v0;
            *(float2*)&out[(size_t)(gi + 8) * HRD + gj] = v1;
        }
}

// ---------------- launch ------------------------------------------------------
#define DYNSMEM (4 * TILEF * 4)   // 2 buffers x 2 tiles x 128x36 floats = 73728 B

extern "C" void kernel_launch(void* const* d_in, const int* in_sizes, int n_in,
                              void* d_out, int out_size)
{
    const float* lrx = (const float*)d_in[0];
    const float* Wq  = (const float*)d_in[1];
    const float* bq  = (const float*)d_in[2];
    const float* Wk  = (const float*)d_in[3];
    const float* bk  = (const float*)d_in[4];
    const float* Wv  = (const float*)d_in[5];
    const float* bv  = (const float*)d_in[6];
    const float* Ws  = (const float*)d_in[7];
    const float* bs  = (const float*)d_in[8];
    const float* gw  = (const float*)d_in[9];
    const float* gb  = (const float*)d_in[10];
    const float* gms = (const float*)d_in[11];

    cudaFuncSetAttribute(proj_tc,   cudaFuncAttributeMaxDynamicSharedMemorySize, DYNSMEM);
    cudaFuncSetAttribute(scores_tc, cudaFuncAttributeMaxDynamicSharedMemorySize, DYNSMEM);
    cudaFuncSetAttribute(pv_tc,     cudaFuncAttributeMaxDynamicSharedMemorySize, DYNSMEM);
    cudaFuncSetAttribute(gram_tc,   cudaFuncAttributeMaxDynamicSharedMemorySize, DYNSMEM);

    dim3 t(NT);
    proj_tc   <<<dim3(HRD / 128, NND / 128, 4),     t, DYNSMEM>>>(lrx, Wq, bq, Wk, bk, Wv, bv, Ws, bs);
    scores_tc <<<dim3(NND / 128, NND / 128, HEADS), t, DYNSMEM>>>();
    softmax_kernel<<<HEADS * NND, t>>>();
    pv_tc     <<<dim3(CH / 128, NND / 128, HEADS),  t, DYNSMEM>>>();
    stats1_kernel <<<dim3(HRD / 256, NND / 128), t>>>();
    stats2_kernel <<<HRD / 256, t>>>(gw, gb, gms);
    gram_tc   <<<dim3(HRD / 128, HRD / 128), t, DYNSMEM>>>((float*)d_out);
}

// round 5
// speedup vs baseline: 5.4344x; 1.5424x over previous
#include <cuda_runtime.h>
#include <math.h>
#include <stdint.h>

#define LRD   512
#define HRD   2048
#define HEADS 4
#define CH    512
#define NND   4096
#define EPSG  1e-5f
#define NT    256

#define DSTR  36            // direct-layout smem row stride (floats): conflict-free frags
#define KSTR  136           // k-major stride: 136 mod 32 = 8 -> 8*tg+gp all distinct
#define DTF   (128 * DSTR)  // direct tile floats
#define KTF   (32 * KSTR)   // k-major tile floats

// ---------------- scratch (__device__ globals: allocation-free) --------------
__device__ float g_LRr[LRD * NND];          // rounded lr_x (2M elements)
__device__ float g_Wr [4][LRD * HRD];       // rounded Wq,Wk,Wv,Wskip
__device__ float g_Q [NND * HRD];
__device__ float g_K [NND * HRD];
__device__ float g_V [NND * HRD];
__device__ float g_SK[NND * HRD];
__device__ float g_S [(size_t)HEADS * NND * NND];
__device__ float g_O [NND * HRD];
__device__ float g_psum[32 * HRD];
__device__ float g_psq [32 * HRD];
__device__ float g_sum[HRD];
__device__ float g_a  [HRD];
__device__ float g_c  [HRD];

// ---------------- helpers ----------------------------------------------------
__device__ __forceinline__ float tf32f(float f) {
    uint32_t u; asm("cvt.rna.tf32.f32 %0, %1;" : "=r"(u) : "f"(f));
    return __uint_as_float(u);
}
__device__ __forceinline__ uint32_t su32(const void* p) {
    uint32_t a;
    asm("{ .reg .u64 t; cvta.to.shared.u64 t, %1; cvt.u32.u64 %0, t; }" : "=r"(a) : "l"(p));
    return a;
}
#define CPA16(dst, src) asm volatile("cp.async.cg.shared.global [%0], [%1], 16;" :: "r"(dst), "l"(src))
#define CP_COMMIT()     asm volatile("cp.async.commit_group;" ::: "memory")
#define CP_WAIT(n)      asm volatile("cp.async.wait_group %0;" :: "n"(n) : "memory")

__device__ __forceinline__ void mma8(float* c, const uint32_t* a, const uint32_t* b) {
    asm volatile(
        "mma.sync.aligned.m16n8k8.row.col.f32.tf32.tf32.f32 "
        "{%0,%1,%2,%3}, {%4,%5,%6,%7}, {%8,%9}, {%0,%1,%2,%3};"
        : "+f"(c[0]), "+f"(c[1]), "+f"(c[2]), "+f"(c[3])
        : "r"(a[0]), "r"(a[1]), "r"(a[2]), "r"(a[3]), "r"(b[0]), "r"(b[1]));
}

// ---------------- GEMM core: C[128x128] = A(128xK) * B(128xK)^T ---------------
// TR=true: operand stored k-major [k][j] in gmem; TR=false: row-major [j][k]
template<int NC, bool TRA, bool TRB>
__device__ __forceinline__ void gemm_core(const float* __restrict__ Ag, int lda, int abase,
                                          const float* __restrict__ Bg, int ldb, int bbase,
                                          float acc[2][8][4]) {
    constexpr int TAF = TRA ? KTF : DTF;
    constexpr int TBF = TRB ? KTF : DTF;
    extern __shared__ float smem[];
    float* Sa = smem;
    float* Sb = smem + 2 * TAF;
    const uint32_t suA = su32(Sa), suB = su32(Sb);
    const int tid = threadIdx.x;

    uint32_t aoff[4], boff[4];
    const float* asrc[4]; const float* bsrc[4];
    size_t astep, bstep;
#pragma unroll
    for (int t = 0; t < 4; t++) {
        int v = tid + t * NT;
        if (TRA) { int k = v >> 5, j = (v & 31) * 4;
            aoff[t] = (k * KSTR + j) * 4; asrc[t] = Ag + (size_t)k * lda + abase + j; }
        else     { int r = v >> 3, q = (v & 7) * 4;
            aoff[t] = (r * DSTR + q) * 4; asrc[t] = Ag + (size_t)(abase + r) * lda + q; }
        if (TRB) { int k = v >> 5, j = (v & 31) * 4;
            boff[t] = (k * KSTR + j) * 4; bsrc[t] = Bg + (size_t)k * ldb + bbase + j; }
        else     { int r = v >> 3, q = (v & 7) * 4;
            boff[t] = (r * DSTR + q) * 4; bsrc[t] = Bg + (size_t)(bbase + r) * ldb + q; }
    }
    astep = TRA ? (size_t)32 * lda : 32;
    bstep = TRB ? (size_t)32 * ldb : 32;

#pragma unroll
    for (int mf = 0; mf < 2; mf++)
#pragma unroll
        for (int nf = 0; nf < 8; nf++)
#pragma unroll
            for (int e = 0; e < 4; e++) acc[mf][nf][e] = 0.f;

    const int lane = tid & 31, wid = tid >> 5;
    const int gp = lane >> 2, tg = lane & 3;
    const int mw = (wid & 3) * 32, nw = (wid >> 2) * 64;

    auto issue = [&](int i) {
        const uint32_t ab = suA + (uint32_t)((i & 1) * TAF * 4);
        const uint32_t bb = suB + (uint32_t)((i & 1) * TBF * 4);
#pragma unroll
        for (int t = 0; t < 4; t++) CPA16(ab + aoff[t], asrc[t] + (size_t)i * astep);
#pragma unroll
        for (int t = 0; t < 4; t++) CPA16(bb + boff[t], bsrc[t] + (size_t)i * bstep);
        CP_COMMIT();
    };

    issue(0);
#pragma unroll 1
    for (int i = 0; i < NC; i++) {
        if (i + 1 < NC) { issue(i + 1); CP_WAIT(1); }
        else            { CP_WAIT(0); }
        __syncthreads();

        const uint32_t* A = (const uint32_t*)(Sa + (i & 1) * TAF);
        const uint32_t* B = (const uint32_t*)(Sb + (i & 1) * TBF);
#pragma unroll
        for (int ks = 0; ks < 4; ks++) {
            const int k0 = ks * 8;
            uint32_t a[2][4], b[8][2];
#pragma unroll
            for (int mf = 0; mf < 2; mf++) {
                const int r = mw + mf * 16 + gp;
                if (TRA) {
                    const int i0 = (k0 + tg) * KSTR + r;
                    a[mf][0] = A[i0];            a[mf][1] = A[i0 + 8];
                    a[mf][2] = A[i0 + 4 * KSTR]; a[mf][3] = A[i0 + 4 * KSTR + 8];
                } else {
                    const int i0 = r * DSTR + k0 + tg;
                    a[mf][0] = A[i0];            a[mf][1] = A[i0 + 8 * DSTR];
                    a[mf][2] = A[i0 + 4];        a[mf][3] = A[i0 + 8 * DSTR + 4];
                }
            }
#pragma unroll
            for (int nf = 0; nf < 8; nf++) {
                const int n = nw + nf * 8 + gp;
                if (TRB) {
                    const int i0 = (k0 + tg) * KSTR + n;
                    b[nf][0] = B[i0]; b[nf][1] = B[i0 + 4 * KSTR];
                } else {
                    const int i0 = n * DSTR + k0 + tg;
                    b[nf][0] = B[i0]; b[nf][1] = B[i0 + 4];
                }
            }
#pragma unroll
            for (int mf = 0; mf < 2; mf++)
#pragma unroll
                for (int nf = 0; nf < 8; nf++) mma8(acc[mf][nf], a[mf], b[nf]);
        }
        __syncthreads();
    }
}

#define EPI_COORDS                                             \
    const int lane = threadIdx.x & 31, wid = threadIdx.x >> 5; \
    const int gp = lane >> 2, tg = lane & 3;                   \
    const int mw = (wid & 3) * 32, nw = (wid >> 2) * 64;

// ---------------- 0) prepass: round inputs to tf32 (rna) ---------------------
// grid.x must cover LRD*NND (2M) for z==0; W's are LRD*HRD (1M).
__global__ void round_inputs(const float* __restrict__ lrx,
                             const float* __restrict__ Wq, const float* __restrict__ Wk,
                             const float* __restrict__ Wv, const float* __restrict__ Ws)
{
    const int i = blockIdx.x * 256 + threadIdx.x;
    const int z = blockIdx.y;
    if (z == 0) { if (i < LRD * NND) g_LRr[i] = tf32f(lrx[i]); }
    else {
        if (i < LRD * HRD) {
            const float* W = (z == 1) ? Wq : (z == 2) ? Wk : (z == 3) ? Wv : Ws;
            g_Wr[z - 1][i] = tf32f(W[i]);
        }
    }
}

// ---------------- 1) projections (Q,K,V,skip) --------------------------------
__global__ void __launch_bounds__(NT, 2) proj_tc(
    const float* __restrict__ bq, const float* __restrict__ bk,
    const float* __restrict__ bv, const float* __restrict__ bs)
{
    const float* bias; float* out; bool rnd;
    const int z = blockIdx.z;
    if      (z == 0) { bias = bq; out = g_Q;  rnd = true;  }
    else if (z == 1) { bias = bk; out = g_K;  rnd = true;  }
    else if (z == 2) { bias = bv; out = g_V;  rnd = true;  }
    else             { bias = bs; out = g_SK; rnd = false; }

    const int n0 = blockIdx.y * 128, j0 = blockIdx.x * 128;
    float acc[2][8][4];
    gemm_core<LRD / 32, true, true>(g_LRr, NND, n0, g_Wr[z], HRD, j0, acc);

    EPI_COORDS;
#pragma unroll
    for (int mf = 0; mf < 2; mf++)
#pragma unroll
        for (int nf = 0; nf < 8; nf++) {
            int r = n0 + mw + mf * 16 + gp;
            int c = j0 + nw + nf * 8 + 2 * tg;
            float b0 = bias[c], b1 = bias[c + 1];
            float v00 = acc[mf][nf][0] + b0, v01 = acc[mf][nf][1] + b1;
            float v10 = acc[mf][nf][2] + b0, v11 = acc[mf][nf][3] + b1;
            if (rnd) { v00 = tf32f(v00); v01 = tf32f(v01); v10 = tf32f(v10); v11 = tf32f(v11); }
            *(float2*)&out[(size_t)r * HRD + c]       = make_float2(v00, v01);
            *(float2*)&out[(size_t)(r + 8) * HRD + c] = make_float2(v10, v11);
        }
}

// ---------------- 2) scores: S_h = (Q_h K_h^T) / sqrt(C) ---------------------
__global__ void __launch_bounds__(NT, 2) scores_tc()
{
    const int h = blockIdx.z;
    const float* Qp = g_Q + h * CH;
    const float* Kp = g_K + h * CH;
    float* S = g_S + (size_t)h * NND * NND;
    const int n0 = blockIdx.y * 128, m0 = blockIdx.x * 128;

    float acc[2][8][4];
    gemm_core<CH / 32, false, false>(Qp, HRD, n0, Kp, HRD, m0, acc);

    const float scale = rsqrtf((float)CH);
    EPI_COORDS;
#pragma unroll
    for (int mf = 0; mf < 2; mf++)
#pragma unroll
        for (int nf = 0; nf < 8; nf++) {
            int r = n0 + mw + mf * 16 + gp;
            int c = m0 + nw + nf * 8 + 2 * tg;
            *(float2*)&S[(size_t)r * NND + c] =
                make_float2(acc[mf][nf][0] * scale, acc[mf][nf][1] * scale);
            *(float2*)&S[(size_t)(r + 8) * NND + c] =
                make_float2(acc[mf][nf][2] * scale, acc[mf][nf][3] * scale);
        }
}

// ---------------- 3) softmax (in place, output rounded to tf32) --------------
__global__ void softmax_kernel()
{
    float* p = g_S + (size_t)blockIdx.x * NND;
    const int tid = threadIdx.x;

    float v[16];
    float mx = -INFINITY;
#pragma unroll
    for (int i = 0; i < 16; i++) { v[i] = p[tid + i * 256]; mx = fmaxf(mx, v[i]); }

    __shared__ float red[256];
    red[tid] = mx; __syncthreads();
    for (int s = 128; s > 0; s >>= 1) {
        if (tid < s) red[tid] = fmaxf(red[tid], red[tid + s]);
        __syncthreads();
    }
    mx = red[0]; __syncthreads();

    float sum = 0.f;
#pragma unroll
    for (int i = 0; i < 16; i++) { v[i] = __expf(v[i] - mx); sum += v[i]; }

    red[tid] = sum; __syncthreads();
    for (int s = 128; s > 0; s >>= 1) {
        if (tid < s) red[tid] += red[tid + s];
        __syncthreads();
    }
    const float inv = 1.0f / red[0];
#pragma unroll
    for (int i = 0; i < 16; i++) p[tid + i * 256] = tf32f(v[i] * inv);
}

// ---------------- 4) out = P @ V + skip (rounded: gram operand) --------------
__global__ void __launch_bounds__(NT, 2) pv_tc()
{
    const int h = blockIdx.z;
    const float* P = g_S + (size_t)h * NND * NND;
    const float* V = g_V + h * CH;
    const int n0 = blockIdx.y * 128, c0 = blockIdx.x * 128;

    float acc[2][8][4];
    gemm_core<NND / 32, false, true>(P, NND, n0, V, HRD, c0, acc);

    EPI_COORDS;
#pragma unroll
    for (int mf = 0; mf < 2; mf++)
#pragma unroll
        for (int nf = 0; nf < 8; nf++) {
            int r = n0 + mw + mf * 16 + gp;
            int c = h * CH + c0 + nw + nf * 8 + 2 * tg;
            size_t g0 = (size_t)r * HRD + c, g1 = (size_t)(r + 8) * HRD + c;
            float2 s0 = *(const float2*)&g_SK[g0];
            float2 s1 = *(const float2*)&g_SK[g1];
            *(float2*)&g_O[g0] = make_float2(tf32f(acc[mf][nf][0] + s0.x),
                                             tf32f(acc[mf][nf][1] + s0.y));
            *(float2*)&g_O[g1] = make_float2(tf32f(acc[mf][nf][2] + s1.x),
                                             tf32f(acc[mf][nf][3] + s1.y));
        }
}

// ---------------- 5) per-channel stats (deterministic 2-stage) ---------------
__global__ void stats1_kernel()
{
    const int j  = blockIdx.x * 256 + threadIdx.x;
    const int r0 = blockIdx.y * 128;
    float s = 0.f, q = 0.f;
    for (int r = 0; r < 128; r++) {
        float v = g_O[(size_t)(r0 + r) * HRD + j];
        s += v; q = fmaf(v, v, q);
    }
    g_psum[blockIdx.y * HRD + j] = s;
    g_psq [blockIdx.y * HRD + j] = q;
}

__global__ void stats2_kernel(const float* __restrict__ w, const float* __restrict__ b,
                              const float* __restrict__ ms)
{
    const int j = blockIdx.x * 256 + threadIdx.x;
    float s = 0.f, q = 0.f;
    for (int i = 0; i < 32; i++) { s += g_psum[i * HRD + j]; q += g_psq[i * HRD + j]; }
    const float invN = 1.0f / (float)NND;
    const float m    = s * invN;
    const float sc   = ms[j];
    const float var  = q * invN - 2.f * sc * m * m + sc * sc * m * m;
    const float rstd = rsqrtf(var + EPSG);
    const float wj = w[j], bj = b[j];
    const float sumc = s - (float)NND * sc * m;
    const float normsq = wj * wj * rstd * rstd * ((float)NND * var)
                       + 2.f * wj * bj * rstd * sumc
                       + (float)NND * bj * bj;
    const float inorm = rsqrtf(normsq);
    g_a[j]   = rstd * wj * inorm;
    g_c[j]   = (bj - sc * m * rstd * wj) * inorm;
    g_sum[j] = s;
}

// ---------------- 6) Gram O^T O with fused affine + relu ---------------------
__global__ void __launch_bounds__(NT, 2) gram_tc(float* __restrict__ out)
{
    const int i0 = blockIdx.y * 128, j0 = blockIdx.x * 128;

    float acc[2][8][4];
    gemm_core<NND / 32, true, true>(g_O, HRD, i0, g_O, HRD, j0, acc);

    EPI_COORDS;
#pragma unroll
    for (int mf = 0; mf < 2; mf++)
#pragma unroll
        for (int nf = 0; nf < 8; nf++) {
            int gi = i0 + mw + mf * 16 + gp;
            int gj = j0 + nw + nf * 8 + 2 * tg;
            float ai0 = g_a[gi],     ci0 = g_c[gi],     Si0 = g_sum[gi];
            float ai1 = g_a[gi + 8], ci1 = g_c[gi + 8], Si1 = g_sum[gi + 8];
            float aj0 = g_a[gj],     cj0 = g_c[gj],     Sj0 = g_sum[gj];
            float aj1 = g_a[gj + 1], cj1 = g_c[gj + 1], Sj1 = g_sum[gj + 1];

            float r00 = ai0 * aj0 * acc[mf][nf][0] + ai0 * cj0 * Si0 + ci0 * aj0 * Sj0 + (float)NND * ci0 * cj0;
            float r01 = ai0 * aj1 * acc[mf][nf][1] + ai0 * cj1 * Si0 + ci0 * aj1 * Sj1 + (float)NND * ci0 * cj1;
            float r10 = ai1 * aj0 * acc[mf][nf][2] + ai1 * cj0 * Si1 + ci1 * aj0 * Sj0 + (float)NND * ci1 * cj0;
            float r11 = ai1 * aj1 * acc[mf][nf][3] + ai1 * cj1 * Si1 + ci1 * aj1 * Sj1 + (float)NND * ci1 * cj1;

            *(float2*)&out[(size_t)gi * HRD + gj]       = make_float2(fmaxf(r00, 0.f), fmaxf(r01, 0.f));
            *(float2*)&out[(size_t)(gi + 8) * HRD + gj] = make_float2(fmaxf(r10, 0.f), fmaxf(r11, 0.f));
        }
}

// ---------------- launch ------------------------------------------------------
#define DYNSMEM (4 * DTF * 4)   // worst case (scores, both direct): 73728 B

extern "C" void kernel_launch(void* const* d_in, const int* in_sizes, int n_in,
                              void* d_out, int out_size)
{
    const float* lrx = (const float*)d_in[0];
    const float* Wq  = (const float*)d_in[1];
    const float* bq  = (const float*)d_in[2];
    const float* Wk  = (const float*)d_in[3];
    const float* bk  = (const float*)d_in[4];
    const float* Wv  = (const float*)d_in[5];
    const float* bv  = (const float*)d_in[6];
    const float* Ws  = (const float*)d_in[7];
    const float* bs  = (const float*)d_in[8];
    const float* gw  = (const float*)d_in[9];
    const float* gb  = (const float*)d_in[10];
    const float* gms = (const float*)d_in[11];

    cudaFuncSetAttribute(proj_tc,   cudaFuncAttributeMaxDynamicSharedMemorySize, DYNSMEM);
    cudaFuncSetAttribute(scores_tc, cudaFuncAttributeMaxDynamicSharedMemorySize, DYNSMEM);
    cudaFuncSetAttribute(pv_tc,     cudaFuncAttributeMaxDynamicSharedMemorySize, DYNSMEM);
    cudaFuncSetAttribute(gram_tc,   cudaFuncAttributeMaxDynamicSharedMemorySize, DYNSMEM);

    dim3 t(NT);
    round_inputs<<<dim3((LRD * NND + 255) / 256, 5), t>>>(lrx, Wq, Wk, Wv, Ws);
    proj_tc   <<<dim3(HRD / 128, NND / 128, 4),     t, DYNSMEM>>>(bq, bk, bv, bs);
    scores_tc <<<dim3(NND / 128, NND / 128, HEADS), t, DYNSMEM>>>();
    softmax_kernel<<<HEADS * NND, t>>>();
    pv_tc     <<<dim3(CH / 128, NND / 128, HEADS),  t, DYNSMEM>>>();
    stats1_kernel <<<dim3(HRD / 256, NND / 128), t>>>();
    stats2_kernel <<<HRD / 256, t>>>(gw, gb, gms);
    gram_tc   <<<dim3(HRD / 128, HRD / 128), t, DYNSMEM>>>((float*)d_out);
}

// round 6
// speedup vs baseline: 9.2801x; 1.7077x over previous
#include <cuda_runtime.h>
#include <cuda_fp16.h>
#include <math.h>
#include <stdint.h>

#define LRD   512
#define HRD   2048
#define HEADS 4
#define CH    512
#define NND   4096
#define EPSG  1e-5f
#define NT    256

#define KCH   64            // k per smem chunk (4 x k16 steps)
#define STRH  72            // smem row stride in halves: u32 stride 36 -> conflict-free
#define TFH   (128 * STRH)  // halves per tile

// ---------------- scratch (__device__ globals: allocation-free) --------------
__device__ __half g_Xh [NND * LRD];          // lr_x^T, half
__device__ __half g_Wh [4][(size_t)HRD * LRD]; // W^T, half
__device__ __half g_Qh [NND * HRD];
__device__ __half g_Kh [NND * HRD];
__device__ __half g_Vh [NND * HRD];
__device__ __half g_VTh[(size_t)HRD * NND];  // V^T (rows j=h*CH+c, cols m)
__device__ float  g_SK [NND * HRD];
__device__ float  g_S  [(size_t)HEADS * NND * NND];   // raw scaled scores, fp32
__device__ __half g_Ph [(size_t)HEADS * NND * NND];   // probs, half (128 MB)
__device__ float  g_O  [NND * HRD];
__device__ __half g_OTh[(size_t)HRD * NND];  // O^T, half
__device__ float  g_psum[32 * HRD];
__device__ float  g_psq [32 * HRD];
__device__ float  g_sum[HRD];
__device__ float  g_a  [HRD];
__device__ float  g_c  [HRD];

// ---------------- helpers ----------------------------------------------------
__device__ __forceinline__ uint32_t su32(const void* p) {
    uint32_t a;
    asm("{ .reg .u64 t; cvta.to.shared.u64 t, %1; cvt.u32.u64 %0, t; }" : "=r"(a) : "l"(p));
    return a;
}
#define CPA16(dst, src) asm volatile("cp.async.cg.shared.global [%0], [%1], 16;" :: "r"(dst), "l"(src))
#define CP_COMMIT()     asm volatile("cp.async.commit_group;" ::: "memory")
#define CP_WAIT(n)      asm volatile("cp.async.wait_group %0;" :: "n"(n) : "memory")

__device__ __forceinline__ void mma16(float* c, const uint32_t* a, const uint32_t* b) {
    asm volatile(
        "mma.sync.aligned.m16n8k16.row.col.f32.f16.f16.f32 "
        "{%0,%1,%2,%3}, {%4,%5,%6,%7}, {%8,%9}, {%0,%1,%2,%3};"
        : "+f"(c[0]), "+f"(c[1]), "+f"(c[2]), "+f"(c[3])
        : "r"(a[0]), "r"(a[1]), "r"(a[2]), "r"(a[3]), "r"(b[0]), "r"(b[1]));
}

// ---------------- GEMM core: C[128x128] = A(128xK) * B(128xK)^T ---------------
// Both operands half, row-major with contiguous k (direct). Ag/Bg point at
// (row0, k0=0); lda/ldb in halves.
template<int NC>
__device__ __forceinline__ void gemm_h(const __half* __restrict__ Ag, int lda,
                                       const __half* __restrict__ Bg, int ldb,
                                       float acc[2][8][4]) {
    extern __shared__ __align__(16) char dynsmem[];
    __half* Sa = (__half*)dynsmem;
    __half* Sb = Sa + 2 * TFH;
    const uint32_t suA = su32(Sa), suB = su32(Sb);
    const int tid = threadIdx.x;

    // copy descriptors: 4 x 16B (8 halves) per tile per thread
    uint32_t aoff[4], boff[4];
    const __half* asrc[4]; const __half* bsrc[4];
#pragma unroll
    for (int t = 0; t < 4; t++) {
        int v = tid + t * NT;
        int r = v >> 3, q = v & 7;
        aoff[t] = (r * STRH + q * 8) * 2;
        boff[t] = aoff[t];
        asrc[t] = Ag + (size_t)r * lda + q * 8;
        bsrc[t] = Bg + (size_t)r * ldb + q * 8;
    }

#pragma unroll
    for (int mf = 0; mf < 2; mf++)
#pragma unroll
        for (int nf = 0; nf < 8; nf++)
#pragma unroll
            for (int e = 0; e < 4; e++) acc[mf][nf][e] = 0.f;

    const int lane = tid & 31, wid = tid >> 5;
    const int gp = lane >> 2, tg = lane & 3;
    const int mw = (wid & 3) * 32, nw = (wid >> 2) * 64;

    auto issue = [&](int i) {
        const uint32_t ab = suA + (uint32_t)((i & 1) * TFH * 2);
        const uint32_t bb = suB + (uint32_t)((i & 1) * TFH * 2);
        const size_t ko = (size_t)i * KCH;
#pragma unroll
        for (int t = 0; t < 4; t++) CPA16(ab + aoff[t], asrc[t] + ko);
#pragma unroll
        for (int t = 0; t < 4; t++) CPA16(bb + boff[t], bsrc[t] + ko);
        CP_COMMIT();
    };

    issue(0);
#pragma unroll 1
    for (int i = 0; i < NC; i++) {
        if (i + 1 < NC) { issue(i + 1); CP_WAIT(1); }
        else            { CP_WAIT(0); }
        __syncthreads();

        const uint32_t* A = (const uint32_t*)(Sa + (i & 1) * TFH);
        const uint32_t* B = (const uint32_t*)(Sb + (i & 1) * TFH);
#pragma unroll
        for (int ks = 0; ks < 4; ks++) {
            uint32_t a[2][4], b[8][2];
#pragma unroll
            for (int mf = 0; mf < 2; mf++) {
                const int r = mw + mf * 16 + gp;
                const int i0 = r * 36 + ks * 8 + tg;
                a[mf][0] = A[i0];            a[mf][1] = A[i0 + 8 * 36];
                a[mf][2] = A[i0 + 4];        a[mf][3] = A[i0 + 8 * 36 + 4];
            }
#pragma unroll
            for (int nf = 0; nf < 8; nf++) {
                const int n = nw + nf * 8 + gp;
                const int i0 = n * 36 + ks * 8 + tg;
                b[nf][0] = B[i0]; b[nf][1] = B[i0 + 4];
            }
#pragma unroll
            for (int mf = 0; mf < 2; mf++)
#pragma unroll
                for (int nf = 0; nf < 8; nf++) mma16(acc[mf][nf], a[mf], b[nf]);
        }
        __syncthreads();
    }
}

#define EPI_COORDS                                             \
    const int lane = threadIdx.x & 31, wid = threadIdx.x >> 5; \
    const int gp = lane >> 2, tg = lane & 3;                   \
    const int mw = (wid & 3) * 32, nw = (wid >> 2) * 64;

// ---------------- transpose kernels ------------------------------------------
// src fp32 [R][C] -> dst half [C][R]
__global__ void xpose_f2h(const float* __restrict__ src, __half* __restrict__ dst,
                          int R, int C)
{
    __shared__ float t[32][33];
    const int bx = blockIdx.x * 32, by = blockIdx.y * 32;
    const int tx = threadIdx.x & 31, ty = threadIdx.x >> 5;
#pragma unroll
    for (int i = 0; i < 4; i++)
        t[ty + i * 8][tx] = src[(size_t)(by + ty + i * 8) * C + bx + tx];
    __syncthreads();
#pragma unroll
    for (int i = 0; i < 4; i++)
        dst[(size_t)(bx + ty + i * 8) * R + by + tx] = __float2half_rn(t[tx][ty + i * 8]);
}

// src half [R][C] -> dst half [C][R]
__global__ void xpose_h2h(const __half* __restrict__ src, __half* __restrict__ dst,
                          int R, int C)
{
    __shared__ __half t[32][34];
    const int bx = blockIdx.x * 32, by = blockIdx.y * 32;
    const int tx = threadIdx.x & 31, ty = threadIdx.x >> 5;
#pragma unroll
    for (int i = 0; i < 4; i++)
        t[ty + i * 8][tx] = src[(size_t)(by + ty + i * 8) * C + bx + tx];
    __syncthreads();
#pragma unroll
    for (int i = 0; i < 4; i++)
        dst[(size_t)(bx + ty + i * 8) * R + by + tx] = t[tx][ty + i * 8];
}

// ---------------- 1) projections (Q,K,V half; skip fp32) ---------------------
__global__ void __launch_bounds__(NT, 2) proj_h(
    const float* __restrict__ bq, const float* __restrict__ bk,
    const float* __restrict__ bv, const float* __restrict__ bs)
{
    const float* bias; __half* outh = nullptr; float* outf = nullptr;
    const int z = blockIdx.z;
    if      (z == 0) { bias = bq; outh = g_Qh; }
    else if (z == 1) { bias = bk; outh = g_Kh; }
    else if (z == 2) { bias = bv; outh = g_Vh; }
    else             { bias = bs; outf = g_SK; }

    const int n0 = blockIdx.y * 128, j0 = blockIdx.x * 128;
    float acc[2][8][4];
    gemm_h<LRD / KCH>(g_Xh + (size_t)n0 * LRD, LRD,
                      g_Wh[z] + (size_t)j0 * LRD, LRD, acc);

    EPI_COORDS;
#pragma unroll
    for (int mf = 0; mf < 2; mf++)
#pragma unroll
        for (int nf = 0; nf < 8; nf++) {
            int r = n0 + mw + mf * 16 + gp;
            int c = j0 + nw + nf * 8 + 2 * tg;
            float b0 = bias[c], b1 = bias[c + 1];
            float v00 = acc[mf][nf][0] + b0, v01 = acc[mf][nf][1] + b1;
            float v10 = acc[mf][nf][2] + b0, v11 = acc[mf][nf][3] + b1;
            if (outh) {
                *(half2*)&outh[(size_t)r * HRD + c]       = __floats2half2_rn(v00, v01);
                *(half2*)&outh[(size_t)(r + 8) * HRD + c] = __floats2half2_rn(v10, v11);
            } else {
                *(float2*)&outf[(size_t)r * HRD + c]       = make_float2(v00, v01);
                *(float2*)&outf[(size_t)(r + 8) * HRD + c] = make_float2(v10, v11);
            }
        }
}

// ---------------- 2) scores: S_h = (Q_h K_h^T) / sqrt(C), fp32 out -----------
__global__ void __launch_bounds__(NT, 2) scores_h()
{
    const int h = blockIdx.z;
    float* S = g_S + (size_t)h * NND * NND;
    const int n0 = blockIdx.y * 128, m0 = blockIdx.x * 128;

    float acc[2][8][4];
    gemm_h<CH / KCH>(g_Qh + (size_t)n0 * HRD + h * CH, HRD,
                     g_Kh + (size_t)m0 * HRD + h * CH, HRD, acc);

    const float scale = rsqrtf((float)CH);
    EPI_COORDS;
#pragma unroll
    for (int mf = 0; mf < 2; mf++)
#pragma unroll
        for (int nf = 0; nf < 8; nf++) {
            int r = n0 + mw + mf * 16 + gp;
            int c = m0 + nw + nf * 8 + 2 * tg;
            *(float2*)&S[(size_t)r * NND + c] =
                make_float2(acc[mf][nf][0] * scale, acc[mf][nf][1] * scale);
            *(float2*)&S[(size_t)(r + 8) * NND + c] =
                make_float2(acc[mf][nf][2] * scale, acc[mf][nf][3] * scale);
        }
}

// ---------------- 3) softmax: fp32 S row -> half P row -----------------------
__global__ void softmax_kernel()
{
    const float* p = g_S + (size_t)blockIdx.x * NND;
    __half* ph = g_Ph + (size_t)blockIdx.x * NND;
    const int tid = threadIdx.x;

    float v[16];
    float mx = -INFINITY;
#pragma unroll
    for (int i = 0; i < 16; i++) { v[i] = p[tid + i * 256]; mx = fmaxf(mx, v[i]); }

    __shared__ float red[256];
    red[tid] = mx; __syncthreads();
    for (int s = 128; s > 0; s >>= 1) {
        if (tid < s) red[tid] = fmaxf(red[tid], red[tid + s]);
        __syncthreads();
    }
    mx = red[0]; __syncthreads();

    float sum = 0.f;
#pragma unroll
    for (int i = 0; i < 16; i++) { v[i] = __expf(v[i] - mx); sum += v[i]; }

    red[tid] = sum; __syncthreads();
    for (int s = 128; s > 0; s >>= 1) {
        if (tid < s) red[tid] += red[tid + s];
        __syncthreads();
    }
    const float inv = 1.0f / red[0];
#pragma unroll
    for (int i = 0; i < 16; i++) ph[tid + i * 256] = __float2half_rn(v[i] * inv);
}

// ---------------- 4) out = P @ V + skip (fp32 out) ---------------------------
__global__ void __launch_bounds__(NT, 2) pv_h()
{
    const int h = blockIdx.z;
    const int n0 = blockIdx.y * 128, c0 = blockIdx.x * 128;

    float acc[2][8][4];
    gemm_h<NND / KCH>(g_Ph + (size_t)h * NND * NND + (size_t)n0 * NND, NND,
                      g_VTh + (size_t)(h * CH + c0) * NND, NND, acc);

    EPI_COORDS;
#pragma unroll
    for (int mf = 0; mf < 2; mf++)
#pragma unroll
        for (int nf = 0; nf < 8; nf++) {
            int r = n0 + mw + mf * 16 + gp;
            int c = h * CH + c0 + nw + nf * 8 + 2 * tg;
            size_t g0 = (size_t)r * HRD + c, g1 = (size_t)(r + 8) * HRD + c;
            float2 s0 = *(const float2*)&g_SK[g0];
            float2 s1 = *(const float2*)&g_SK[g1];
            *(float2*)&g_O[g0] = make_float2(acc[mf][nf][0] + s0.x, acc[mf][nf][1] + s0.y);
            *(float2*)&g_O[g1] = make_float2(acc[mf][nf][2] + s1.x, acc[mf][nf][3] + s1.y);
        }
}

// ---------------- 5) per-channel stats (deterministic 2-stage) ---------------
__global__ void stats1_kernel()
{
    const int j  = blockIdx.x * 256 + threadIdx.x;
    const int r0 = blockIdx.y * 128;
    float s = 0.f, q = 0.f;
    for (int r = 0; r < 128; r++) {
        float v = g_O[(size_t)(r0 + r) * HRD + j];
        s += v; q = fmaf(v, v, q);
    }
    g_psum[blockIdx.y * HRD + j] = s;
    g_psq [blockIdx.y * HRD + j] = q;
}

__global__ void stats2_kernel(const float* __restrict__ w, const float* __restrict__ b,
                              const float* __restrict__ ms)
{
    const int j = blockIdx.x * 256 + threadIdx.x;
    float s = 0.f, q = 0.f;
    for (int i = 0; i < 32; i++) { s += g_psum[i * HRD + j]; q += g_psq[i * HRD + j]; }
    const float invN = 1.0f / (float)NND;
    const float m    = s * invN;
    const float sc   = ms[j];
    const float var  = q * invN - 2.f * sc * m * m + sc * sc * m * m;
    const float rstd = rsqrtf(var + EPSG);
    const float wj = w[j], bj = b[j];
    const float sumc = s - (float)NND * sc * m;
    const float normsq = wj * wj * rstd * rstd * ((float)NND * var)
                       + 2.f * wj * bj * rstd * sumc
                       + (float)NND * bj * bj;
    const float inorm = rsqrtf(normsq);
    g_a[j]   = rstd * wj * inorm;
    g_c[j]   = (bj - sc * m * rstd * wj) * inorm;
    g_sum[j] = s;
}

// ---------------- 6) Gram O^T O with fused affine + relu ---------------------
__global__ void __launch_bounds__(NT, 2) gram_h(float* __restrict__ out)
{
    const int i0 = blockIdx.y * 128, j0 = blockIdx.x * 128;

    float acc[2][8][4];
    gemm_h<NND / KCH>(g_OTh + (size_t)i0 * NND, NND,
                      g_OTh + (size_t)j0 * NND, NND, acc);

    EPI_COORDS;
#pragma unroll
    for (int mf = 0; mf < 2; mf++)
#pragma unroll
        for (int nf = 0; nf < 8; nf++) {
            int gi = i0 + mw + mf * 16 + gp;
            int gj = j0 + nw + nf * 8 + 2 * tg;
            float ai0 = g_a[gi],     ci0 = g_c[gi],     Si0 = g_sum[gi];
            float ai1 = g_a[gi + 8], ci1 = g_c[gi + 8], Si1 = g_sum[gi + 8];
            float aj0 = g_a[gj],     cj0 = g_c[gj],     Sj0 = g_sum[gj];
            float aj1 = g_a[gj + 1], cj1 = g_c[gj + 1], Sj1 = g_sum[gj + 1];

            float r00 = ai0 * aj0 * acc[mf][nf][0] + ai0 * cj0 * Si0 + ci0 * aj0 * Sj0 + (float)NND * ci0 * cj0;
            float r01 = ai0 * aj1 * acc[mf][nf][1] + ai0 * cj1 * Si0 + ci0 * aj1 * Sj1 + (float)NND * ci0 * cj1;
            float r10 = ai1 * aj0 * acc[mf][nf][2] + ai1 * cj0 * Si1 + ci1 * aj0 * Sj0 + (float)NND * ci1 * cj0;
            float r11 = ai1 * aj1 * acc[mf][nf][3] + ai1 * cj1 * Si1 + ci1 * aj1 * Sj1 + (float)NND * ci1 * cj1;

            *(float2*)&out[(size_t)gi * HRD + gj]       = make_float2(fmaxf(r00, 0.f), fmaxf(r01, 0.f));
            *(float2*)&out[(size_t)(gi + 8) * HRD + gj] = make_float2(fmaxf(r10, 0.f), fmaxf(r11, 0.f));
        }
}

// ---------------- launch ------------------------------------------------------
#define DYNSMEM (4 * TFH * 2)   // 2 ops x 2 bufs x 128x72 halves = 73728 B

extern "C" void kernel_launch(void* const* d_in, const int* in_sizes, int n_in,
                              void* d_out, int out_size)
{
    const float* lrx = (const float*)d_in[0];
    const float* Wq  = (const float*)d_in[1];
    const float* bq  = (const float*)d_in[2];
    const float* Wk  = (const float*)d_in[3];
    const float* bk  = (const float*)d_in[4];
    const float* Wv  = (const float*)d_in[5];
    const float* bv  = (const float*)d_in[6];
    const float* Ws  = (const float*)d_in[7];
    const float* bs  = (const float*)d_in[8];
    const float* gw  = (const float*)d_in[9];
    const float* gb  = (const float*)d_in[10];
    const float* gms = (const float*)d_in[11];

    cudaFuncSetAttribute(proj_h,   cudaFuncAttributeMaxDynamicSharedMemorySize, DYNSMEM);
    cudaFuncSetAttribute(scores_h, cudaFuncAttributeMaxDynamicSharedMemorySize, DYNSMEM);
    cudaFuncSetAttribute(pv_h,     cudaFuncAttributeMaxDynamicSharedMemorySize, DYNSMEM);
    cudaFuncSetAttribute(gram_h,   cudaFuncAttributeMaxDynamicSharedMemorySize, DYNSMEM);

    __half* whp;  cudaGetSymbolAddress((void**)&whp,  g_Wh);
    __half* xhp;  cudaGetSymbolAddress((void**)&xhp,  g_Xh);
    __half* vhp;  cudaGetSymbolAddress((void**)&vhp,  g_Vh);
    __half* vthp; cudaGetSymbolAddress((void**)&vthp, g_VTh);
    __half* othp; cudaGetSymbolAddress((void**)&othp, g_OTh);
    float*  ofp;  cudaGetSymbolAddress((void**)&ofp,  g_O);

    dim3 t(NT);
    // prepass transposes (fp32 -> half)
    xpose_f2h<<<dim3(NND / 32, LRD / 32), t>>>(lrx, xhp, LRD, NND);
    xpose_f2h<<<dim3(HRD / 32, LRD / 32), t>>>(Wq, whp + 0 * (size_t)HRD * LRD, LRD, HRD);
    xpose_f2h<<<dim3(HRD / 32, LRD / 32), t>>>(Wk, whp + 1 * (size_t)HRD * LRD, LRD, HRD);
    xpose_f2h<<<dim3(HRD / 32, LRD / 32), t>>>(Wv, whp + 2 * (size_t)HRD * LRD, LRD, HRD);
    xpose_f2h<<<dim3(HRD / 32, LRD / 32), t>>>(Ws, whp + 3 * (size_t)HRD * LRD, LRD, HRD);

    proj_h    <<<dim3(HRD / 128, NND / 128, 4),     t, DYNSMEM>>>(bq, bk, bv, bs);
    xpose_h2h <<<dim3(HRD / 32, NND / 32), t>>>(vhp, vthp, NND, HRD);
    scores_h  <<<dim3(NND / 128, NND / 128, HEADS), t, DYNSMEM>>>();
    softmax_kernel<<<HEADS * NND, t>>>();
    pv_h      <<<dim3(CH / 128, NND / 128, HEADS),  t, DYNSMEM>>>();
    stats1_kernel <<<dim3(HRD / 256, NND / 128), t>>>();
    stats2_kernel <<<HRD / 256, t>>>(gw, gb, gms);
    xpose_f2h <<<dim3(HRD / 32, NND / 32), t>>>(ofp, othp, NND, HRD);
    gram_h    <<<dim3(HRD / 128, HRD / 128), t, DYNSMEM>>>((float*)d_out);
}

// round 7
// speedup vs baseline: 9.8738x; 1.0640x over previous
#include <cuda_runtime.h>
#include <cuda_fp16.h>
#include <math.h>
#include <stdint.h>

#define LRD   512
#define HRD   2048
#define HEADS 4
#define CH    512
#define NND   4096
#define EPSG  1e-5f
#define NT    256

#define KCH   64            // k per smem chunk (4 x k16 steps)
#define STRH  72            // smem row stride in halves (144 B)
#define TFH   (128 * STRH)  // halves per tile

// ---------------- scratch (__device__ globals: allocation-free) --------------
__device__ __half g_Xh [NND * LRD];
__device__ __half g_Wh [4][(size_t)HRD * LRD];
__device__ __half g_Qh [NND * HRD];
__device__ __half g_Kh [NND * HRD];
__device__ __half g_Vh [NND * HRD];
__device__ __half g_VTh[(size_t)HRD * NND];
__device__ float  g_SK [NND * HRD];
__device__ float  g_S  [(size_t)HEADS * NND * NND];
__device__ __half g_Ph [(size_t)HEADS * NND * NND];
__device__ float  g_O  [NND * HRD];
__device__ __half g_OTh[(size_t)HRD * NND];
__device__ float  g_psum[32 * HRD];
__device__ float  g_psq [32 * HRD];
__device__ float  g_sum[HRD];
__device__ float  g_a  [HRD];
__device__ float  g_c  [HRD];

// ---------------- helpers ----------------------------------------------------
__device__ __forceinline__ uint32_t su32(const void* p) {
    uint32_t a;
    asm("{ .reg .u64 t; cvta.to.shared.u64 t, %1; cvt.u32.u64 %0, t; }" : "=r"(a) : "l"(p));
    return a;
}
#define CPA16(dst, src) asm volatile("cp.async.cg.shared.global [%0], [%1], 16;" :: "r"(dst), "l"(src))
#define CP_COMMIT()     asm volatile("cp.async.commit_group;" ::: "memory")
#define CP_WAIT(n)      asm volatile("cp.async.wait_group %0;" :: "n"(n) : "memory")

#define LDSM4(r0, r1, r2, r3, addr) asm volatile( \
    "ldmatrix.sync.aligned.m8n8.x4.shared.b16 {%0,%1,%2,%3}, [%4];" \
    : "=r"(r0), "=r"(r1), "=r"(r2), "=r"(r3) : "r"(addr))

__device__ __forceinline__ void mma16(float* c, const uint32_t* a, const uint32_t* b) {
    asm volatile(
        "mma.sync.aligned.m16n8k16.row.col.f32.f16.f16.f32 "
        "{%0,%1,%2,%3}, {%4,%5,%6,%7}, {%8,%9}, {%0,%1,%2,%3};"
        : "+f"(c[0]), "+f"(c[1]), "+f"(c[2]), "+f"(c[3])
        : "r"(a[0]), "r"(a[1]), "r"(a[2]), "r"(a[3]), "r"(b[0]), "r"(b[1]));
}

// ---------------- GEMM core: C[128x128] = A(128xK) * B(128xK)^T ---------------
template<int NC>
__device__ __forceinline__ void gemm_h(const __half* __restrict__ Ag, int lda,
                                       const __half* __restrict__ Bg, int ldb,
                                       float acc[2][8][4]) {
    extern __shared__ __align__(16) char dynsmem[];
    __half* Sa = (__half*)dynsmem;
    __half* Sb = Sa + 2 * TFH;
    const uint32_t suA = su32(Sa), suB = su32(Sb);
    const int tid = threadIdx.x;

    uint32_t aoff[4], boff[4];
    const __half* asrc[4]; const __half* bsrc[4];
#pragma unroll
    for (int t = 0; t < 4; t++) {
        int v = tid + t * NT;
        int r = v >> 3, q = v & 7;
        aoff[t] = (r * STRH + q * 8) * 2;
        boff[t] = aoff[t];
        asrc[t] = Ag + (size_t)r * lda + q * 8;
        bsrc[t] = Bg + (size_t)r * ldb + q * 8;
    }

#pragma unroll
    for (int mf = 0; mf < 2; mf++)
#pragma unroll
        for (int nf = 0; nf < 8; nf++)
#pragma unroll
            for (int e = 0; e < 4; e++) acc[mf][nf][e] = 0.f;

    const int lane = tid & 31, wid = tid >> 5;
    const int mw = (wid & 3) * 32, nw = (wid >> 2) * 64;
    // ldmatrix per-lane source row/col-offset (bytes)
    const int lrow = ((lane >> 3) & 1) * 8 + (lane & 7);
    const int kofs = (lane >> 4) * 16;
    const uint32_t aL = (uint32_t)((mw + lrow) * 144 + kofs);
    const uint32_t bL = (uint32_t)((nw + lrow) * 144 + kofs);

    auto issue = [&](int i) {
        const uint32_t ab = suA + (uint32_t)((i & 1) * TFH * 2);
        const uint32_t bb = suB + (uint32_t)((i & 1) * TFH * 2);
        const size_t ko = (size_t)i * KCH;
#pragma unroll
        for (int t = 0; t < 4; t++) CPA16(ab + aoff[t], asrc[t] + ko);
#pragma unroll
        for (int t = 0; t < 4; t++) CPA16(bb + boff[t], bsrc[t] + ko);
        CP_COMMIT();
    };

    issue(0);
#pragma unroll 1
    for (int i = 0; i < NC; i++) {
        if (i + 1 < NC) { issue(i + 1); CP_WAIT(1); }
        else            { CP_WAIT(0); }
        __syncthreads();

        const uint32_t Ab = suA + (uint32_t)((i & 1) * TFH * 2) + aL;
        const uint32_t Bb = suB + (uint32_t)((i & 1) * TFH * 2) + bL;
#pragma unroll
        for (int ks = 0; ks < 4; ks++) {
            const uint32_t ko = ks * 32;
            uint32_t a[2][4], b[8][2];
            LDSM4(a[0][0], a[0][1], a[0][2], a[0][3], Ab + ko);
            LDSM4(a[1][0], a[1][1], a[1][2], a[1][3], Ab + 16 * 144 + ko);
#pragma unroll
            for (int nf2 = 0; nf2 < 4; nf2++) {
                uint32_t q0, q1, q2, q3;
                LDSM4(q0, q1, q2, q3, Bb + nf2 * (16 * 144) + ko);
                b[2 * nf2][0] = q0; b[2 * nf2 + 1][0] = q1;
                b[2 * nf2][1] = q2; b[2 * nf2 + 1][1] = q3;
            }
#pragma unroll
            for (int mf = 0; mf < 2; mf++)
#pragma unroll
                for (int nf = 0; nf < 8; nf++) mma16(acc[mf][nf], a[mf], b[nf]);
        }
        __syncthreads();
    }
}

#define EPI_COORDS                                             \
    const int lane = threadIdx.x & 31, wid = threadIdx.x >> 5; \
    const int gp = lane >> 2, tg = lane & 3;                   \
    const int mw = (wid & 3) * 32, nw = (wid >> 2) * 64;

// ---------------- transpose kernels ------------------------------------------
__global__ void xpose_f2h(const float* __restrict__ src, __half* __restrict__ dst,
                          int R, int C)
{
    __shared__ float t[32][33];
    const int bx = blockIdx.x * 32, by = blockIdx.y * 32;
    const int tx = threadIdx.x & 31, ty = threadIdx.x >> 5;
#pragma unroll
    for (int i = 0; i < 4; i++)
        t[ty + i * 8][tx] = src[(size_t)(by + ty + i * 8) * C + bx + tx];
    __syncthreads();
#pragma unroll
    for (int i = 0; i < 4; i++)
        dst[(size_t)(bx + ty + i * 8) * R + by + tx] = __float2half_rn(t[tx][ty + i * 8]);
}

__global__ void xpose_h2h(const __half* __restrict__ src, __half* __restrict__ dst,
                          int R, int C)
{
    __shared__ __half t[32][34];
    const int bx = blockIdx.x * 32, by = blockIdx.y * 32;
    const int tx = threadIdx.x & 31, ty = threadIdx.x >> 5;
#pragma unroll
    for (int i = 0; i < 4; i++)
        t[ty + i * 8][tx] = src[(size_t)(by + ty + i * 8) * C + bx + tx];
    __syncthreads();
#pragma unroll
    for (int i = 0; i < 4; i++)
        dst[(size_t)(bx + ty + i * 8) * R + by + tx] = t[tx][ty + i * 8];
}

// ---------------- 1) projections (Q,K,V half; skip fp32) ---------------------
__global__ void __launch_bounds__(NT, 2) proj_h(
    const float* __restrict__ bq, const float* __restrict__ bk,
    const float* __restrict__ bv, const float* __restrict__ bs)
{
    const float* bias; __half* outh = nullptr; float* outf = nullptr;
    const int z = blockIdx.z;
    if      (z == 0) { bias = bq; outh = g_Qh; }
    else if (z == 1) { bias = bk; outh = g_Kh; }
    else if (z == 2) { bias = bv; outh = g_Vh; }
    else             { bias = bs; outf = g_SK; }

    const int n0 = blockIdx.y * 128, j0 = blockIdx.x * 128;
    float acc[2][8][4];
    gemm_h<LRD / KCH>(g_Xh + (size_t)n0 * LRD, LRD,
                      g_Wh[z] + (size_t)j0 * LRD, LRD, acc);

    EPI_COORDS;
#pragma unroll
    for (int mf = 0; mf < 2; mf++)
#pragma unroll
        for (int nf = 0; nf < 8; nf++) {
            int r = n0 + mw + mf * 16 + gp;
            int c = j0 + nw + nf * 8 + 2 * tg;
            float b0 = bias[c], b1 = bias[c + 1];
            float v00 = acc[mf][nf][0] + b0, v01 = acc[mf][nf][1] + b1;
            float v10 = acc[mf][nf][2] + b0, v11 = acc[mf][nf][3] + b1;
            if (outh) {
                *(half2*)&outh[(size_t)r * HRD + c]       = __floats2half2_rn(v00, v01);
                *(half2*)&outh[(size_t)(r + 8) * HRD + c] = __floats2half2_rn(v10, v11);
            } else {
                *(float2*)&outf[(size_t)r * HRD + c]       = make_float2(v00, v01);
                *(float2*)&outf[(size_t)(r + 8) * HRD + c] = make_float2(v10, v11);
            }
        }
}

// ---------------- 2) scores ---------------------------------------------------
__global__ void __launch_bounds__(NT, 2) scores_h()
{
    const int h = blockIdx.z;
    float* S = g_S + (size_t)h * NND * NND;
    const int n0 = blockIdx.y * 128, m0 = blockIdx.x * 128;

    float acc[2][8][4];
    gemm_h<CH / KCH>(g_Qh + (size_t)n0 * HRD + h * CH, HRD,
                     g_Kh + (size_t)m0 * HRD + h * CH, HRD, acc);

    const float scale = rsqrtf((float)CH);
    EPI_COORDS;
#pragma unroll
    for (int mf = 0; mf < 2; mf++)
#pragma unroll
        for (int nf = 0; nf < 8; nf++) {
            int r = n0 + mw + mf * 16 + gp;
            int c = m0 + nw + nf * 8 + 2 * tg;
            *(float2*)&S[(size_t)r * NND + c] =
                make_float2(acc[mf][nf][0] * scale, acc[mf][nf][1] * scale);
            *(float2*)&S[(size_t)(r + 8) * NND + c] =
                make_float2(acc[mf][nf][2] * scale, acc[mf][nf][3] * scale);
        }
}

// ---------------- 3) softmax: fp32 S row -> half P row -----------------------
__global__ void softmax_kernel()
{
    const float* p = g_S + (size_t)blockIdx.x * NND;
    __half* ph = g_Ph + (size_t)blockIdx.x * NND;
    const int tid = threadIdx.x;

    float v[16];
    float mx = -INFINITY;
#pragma unroll
    for (int i = 0; i < 16; i++) { v[i] = p[tid + i * 256]; mx = fmaxf(mx, v[i]); }

    __shared__ float red[256];
    red[tid] = mx; __syncthreads();
    for (int s = 128; s > 0; s >>= 1) {
        if (tid < s) red[tid] = fmaxf(red[tid], red[tid + s]);
        __syncthreads();
    }
    mx = red[0]; __syncthreads();

    float sum = 0.f;
#pragma unroll
    for (int i = 0; i < 16; i++) { v[i] = __expf(v[i] - mx); sum += v[i]; }

    red[tid] = sum; __syncthreads();
    for (int s = 128; s > 0; s >>= 1) {
        if (tid < s) red[tid] += red[tid + s];
        __syncthreads();
    }
    const float inv = 1.0f / red[0];
#pragma unroll
    for (int i = 0; i < 16; i++) ph[tid + i * 256] = __float2half_rn(v[i] * inv);
}

// ---------------- 4) out = P @ V + skip --------------------------------------
__global__ void __launch_bounds__(NT, 2) pv_h()
{
    const int h = blockIdx.z;
    const int n0 = blockIdx.y * 128, c0 = blockIdx.x * 128;

    float acc[2][8][4];
    gemm_h<NND / KCH>(g_Ph + (size_t)h * NND * NND + (size_t)n0 * NND, NND,
                      g_VTh + (size_t)(h * CH + c0) * NND, NND, acc);

    EPI_COORDS;
#pragma unroll
    for (int mf = 0; mf < 2; mf++)
#pragma unroll
        for (int nf = 0; nf < 8; nf++) {
            int r = n0 + mw + mf * 16 + gp;
            int c = h * CH + c0 + nw + nf * 8 + 2 * tg;
            size_t g0 = (size_t)r * HRD + c, g1 = (size_t)(r + 8) * HRD + c;
            float2 s0 = *(const float2*)&g_SK[g0];
            float2 s1 = *(const float2*)&g_SK[g1];
            *(float2*)&g_O[g0] = make_float2(acc[mf][nf][0] + s0.x, acc[mf][nf][1] + s0.y);
            *(float2*)&g_O[g1] = make_float2(acc[mf][nf][2] + s1.x, acc[mf][nf][3] + s1.y);
        }
}

// ---------------- 5) per-channel stats ---------------------------------------
__global__ void stats1_kernel()
{
    const int j  = blockIdx.x * 256 + threadIdx.x;
    const int r0 = blockIdx.y * 128;
    float s = 0.f, q = 0.f;
    for (int r = 0; r < 128; r++) {
        float v = g_O[(size_t)(r0 + r) * HRD + j];
        s += v; q = fmaf(v, v, q);
    }
    g_psum[blockIdx.y * HRD + j] = s;
    g_psq [blockIdx.y * HRD + j] = q;
}

__global__ void stats2_kernel(const float* __restrict__ w, const float* __restrict__ b,
                              const float* __restrict__ ms)
{
    const int j = blockIdx.x * 256 + threadIdx.x;
    float s = 0.f, q = 0.f;
    for (int i = 0; i < 32; i++) { s += g_psum[i * HRD + j]; q += g_psq[i * HRD + j]; }
    const float invN = 1.0f / (float)NND;
    const float m    = s * invN;
    const float sc   = ms[j];
    const float var  = q * invN - 2.f * sc * m * m + sc * sc * m * m;
    const float rstd = rsqrtf(var + EPSG);
    const float wj = w[j], bj = b[j];
    const float sumc = s - (float)NND * sc * m;
    const float normsq = wj * wj * rstd * rstd * ((float)NND * var)
                       + 2.f * wj * bj * rstd * sumc
                       + (float)NND * bj * bj;
    const float inorm = rsqrtf(normsq);
    g_a[j]   = rstd * wj * inorm;
    g_c[j]   = (bj - sc * m * rstd * wj) * inorm;
    g_sum[j] = s;
}

// ---------------- 6) Gram: triangular grid + mirrored store ------------------
__global__ void __launch_bounds__(NT, 2) gram_h(float* __restrict__ out)
{
    // decode lower-triangle block (bi >= bj) from linear index
    const int t = blockIdx.x;
    int bi = (int)((sqrtf(8.f * (float)t + 1.f) - 1.f) * 0.5f);
    while ((bi + 1) * (bi + 2) / 2 <= t) bi++;
    while (bi * (bi + 1) / 2 > t) bi--;
    const int bj = t - bi * (bi + 1) / 2;
    const int i0 = bi * 128, j0 = bj * 128;

    float acc[2][8][4];
    gemm_h<NND / KCH>(g_OTh + (size_t)i0 * NND, NND,
                      g_OTh + (size_t)j0 * NND, NND, acc);

    extern __shared__ __align__(16) char dynsmem[];
    float* gs = (float*)dynsmem;          // 128 x 129 staging (reuses GEMM smem)

    EPI_COORDS;
#pragma unroll
    for (int mf = 0; mf < 2; mf++)
#pragma unroll
        for (int nf = 0; nf < 8; nf++) {
            int lr = mw + mf * 16 + gp;
            int lc = nw + nf * 8 + 2 * tg;
            int gi = i0 + lr, gj = j0 + lc;
            float ai0 = g_a[gi],     ci0 = g_c[gi],     Si0 = g_sum[gi];
            float ai1 = g_a[gi + 8], ci1 = g_c[gi + 8], Si1 = g_sum[gi + 8];
            float aj0 = g_a[gj],     cj0 = g_c[gj],     Sj0 = g_sum[gj];
            float aj1 = g_a[gj + 1], cj1 = g_c[gj + 1], Sj1 = g_sum[gj + 1];

            float r00 = fmaxf(ai0 * aj0 * acc[mf][nf][0] + ai0 * cj0 * Si0 + ci0 * aj0 * Sj0 + (float)NND * ci0 * cj0, 0.f);
            float r01 = fmaxf(ai0 * aj1 * acc[mf][nf][1] + ai0 * cj1 * Si0 + ci0 * aj1 * Sj1 + (float)NND * ci0 * cj1, 0.f);
            float r10 = fmaxf(ai1 * aj0 * acc[mf][nf][2] + ai1 * cj0 * Si1 + ci1 * aj0 * Sj0 + (float)NND * ci1 * cj0, 0.f);
            float r11 = fmaxf(ai1 * aj1 * acc[mf][nf][3] + ai1 * cj1 * Si1 + ci1 * aj1 * Sj1 + (float)NND * ci1 * cj1, 0.f);

            *(float2*)&out[(size_t)gi * HRD + gj]       = make_float2(r00, r01);
            *(float2*)&out[(size_t)(gi + 8) * HRD + gj] = make_float2(r10, r11);

            gs[lr * 129 + lc]           = r00;
            gs[lr * 129 + lc + 1]       = r01;
            gs[(lr + 8) * 129 + lc]     = r10;
            gs[(lr + 8) * 129 + lc + 1] = r11;
        }

    if (bi != bj) {
        __syncthreads();
        const int tid = threadIdx.x;
#pragma unroll
        for (int it = 0; it < 64; it++) {
            int v = tid + it * NT;
            int jr = v >> 7, q = v & 127;
            out[(size_t)(j0 + jr) * HRD + i0 + q] = gs[q * 129 + jr];
        }
    }
}

// ---------------- launch ------------------------------------------------------
#define DYNSMEM (4 * TFH * 2)   // 73728 B (also covers gram's 128x129 fp32 stage)
#define NBLK    (HRD / 128)
#define NTRI    (NBLK * (NBLK + 1) / 2)

extern "C" void kernel_launch(void* const* d_in, const int* in_sizes, int n_in,
                              void* d_out, int out_size)
{
    const float* lrx = (const float*)d_in[0];
    const float* Wq  = (const float*)d_in[1];
    const float* bq  = (const float*)d_in[2];
    const float* Wk  = (const float*)d_in[3];
    const float* bk  = (const float*)d_in[4];
    const float* Wv  = (const float*)d_in[5];
    const float* bv  = (const float*)d_in[6];
    const float* Ws  = (const float*)d_in[7];
    const float* bs  = (const float*)d_in[8];
    const float* gw  = (const float*)d_in[9];
    const float* gb  = (const float*)d_in[10];
    const float* gms = (const float*)d_in[11];

    cudaFuncSetAttribute(proj_h,   cudaFuncAttributeMaxDynamicSharedMemorySize, DYNSMEM);
    cudaFuncSetAttribute(scores_h, cudaFuncAttributeMaxDynamicSharedMemorySize, DYNSMEM);
    cudaFuncSetAttribute(pv_h,     cudaFuncAttributeMaxDynamicSharedMemorySize, DYNSMEM);
    cudaFuncSetAttribute(gram_h,   cudaFuncAttributeMaxDynamicSharedMemorySize, DYNSMEM);

    __half* whp;  cudaGetSymbolAddress((void**)&whp,  g_Wh);
    __half* xhp;  cudaGetSymbolAddress((void**)&xhp,  g_Xh);
    __half* vhp;  cudaGetSymbolAddress((void**)&vhp,  g_Vh);
    __half* vthp; cudaGetSymbolAddress((void**)&vthp, g_VTh);
    __half* othp; cudaGetSymbolAddress((void**)&othp, g_OTh);
    float*  ofp;  cudaGetSymbolAddress((void**)&ofp,  g_O);

    dim3 t(NT);
    xpose_f2h<<<dim3(NND / 32, LRD / 32), t>>>(lrx, xhp, LRD, NND);
    xpose_f2h<<<dim3(HRD / 32, LRD / 32), t>>>(Wq, whp + 0 * (size_t)HRD * LRD, LRD, HRD);
    xpose_f2h<<<dim3(HRD / 32, LRD / 32), t>>>(Wk, whp + 1 * (size_t)HRD * LRD, LRD, HRD);
    xpose_f2h<<<dim3(HRD / 32, LRD / 32), t>>>(Wv, whp + 2 * (size_t)HRD * LRD, LRD, HRD);
    xpose_f2h<<<dim3(HRD / 32, LRD / 32), t>>>(Ws, whp + 3 * (size_t)HRD * LRD, LRD, HRD);

    proj_h    <<<dim3(HRD / 128, NND / 128, 4),     t, DYNSMEM>>>(bq, bk, bv, bs);
    xpose_h2h <<<dim3(HRD / 32, NND / 32), t>>>(vhp, vthp, NND, HRD);
    scores_h  <<<dim3(NND / 128, NND / 128, HEADS), t, DYNSMEM>>>();
    softmax_kernel<<<HEADS * NND, t>>>();
    pv_h      <<<dim3(CH / 128, NND / 128, HEADS),  t, DYNSMEM>>>();
    stats1_kernel <<<dim3(HRD / 256, NND / 128), t>>>();
    stats2_kernel <<<HRD / 256, t>>>(gw, gb, gms);
    xpose_f2h <<<dim3(HRD / 32, NND / 32), t>>>(ofp, othp, NND, HRD);
    gram_h    <<<NTRI, t, DYNSMEM>>>((float*)d_out);
}

// round 8
// speedup vs baseline: 9.9896x; 1.0117x over previous
#include <cuda_runtime.h>
#include <cuda_fp16.h>
#include <math.h>
#include <stdint.h>

#define LRD   512
#define HRD   2048
#define HEADS 4
#define CH    512
#define NND   4096
#define EPSG  1e-5f
#define NT    256

#define KCH   64            // k per smem chunk (4 x k16 steps)
#define STRH  72            // smem row stride in halves (144 B)
#define TFH   (128 * STRH)  // halves per tile
#define NSTG  3             // pipeline stages

// ---------------- scratch (__device__ globals: allocation-free) --------------
__device__ __half g_Xh [NND * LRD];
__device__ __half g_Wh [4][(size_t)HRD * LRD];
__device__ __half g_Qh [NND * HRD];
__device__ __half g_Kh [NND * HRD];
__device__ __half g_Vh [NND * HRD];
__device__ __half g_VTh[(size_t)HRD * NND];
__device__ float  g_SK [NND * HRD];
__device__ __half g_Sh [(size_t)HEADS * NND * NND];  // scores -> probs (in place)
__device__ float  g_O  [NND * HRD];
__device__ __half g_OTh[(size_t)HRD * NND];
__device__ float  g_psum[32 * HRD];
__device__ float  g_psq [32 * HRD];
__device__ float  g_sum[HRD];
__device__ float  g_a  [HRD];
__device__ float  g_c  [HRD];

// ---------------- helpers ----------------------------------------------------
__device__ __forceinline__ uint32_t su32(const void* p) {
    uint32_t a;
    asm("{ .reg .u64 t; cvta.to.shared.u64 t, %1; cvt.u32.u64 %0, t; }" : "=r"(a) : "l"(p));
    return a;
}
#define CPA16(dst, src) asm volatile("cp.async.cg.shared.global [%0], [%1], 16;" :: "r"(dst), "l"(src))
#define CP_COMMIT()     asm volatile("cp.async.commit_group;" ::: "memory")
#define CP_WAIT(n)      asm volatile("cp.async.wait_group %0;" :: "n"(n) : "memory")

#define LDSM4(r0, r1, r2, r3, addr) asm volatile( \
    "ldmatrix.sync.aligned.m8n8.x4.shared.b16 {%0,%1,%2,%3}, [%4];" \
    : "=r"(r0), "=r"(r1), "=r"(r2), "=r"(r3) : "r"(addr))

__device__ __forceinline__ void mma16(float* c, const uint32_t* a, const uint32_t* b) {
    asm volatile(
        "mma.sync.aligned.m16n8k16.row.col.f32.f16.f16.f32 "
        "{%0,%1,%2,%3}, {%4,%5,%6,%7}, {%8,%9}, {%0,%1,%2,%3};"
        : "+f"(c[0]), "+f"(c[1]), "+f"(c[2]), "+f"(c[3])
        : "r"(a[0]), "r"(a[1]), "r"(a[2]), "r"(a[3]), "r"(b[0]), "r"(b[1]));
}

// ---------------- GEMM core: C[128x128] = A(128xK) * B(128xK)^T ---------------
// 3-stage cp.async pipeline, single __syncthreads per chunk.
template<int NC>
__device__ __forceinline__ void gemm_h(const __half* __restrict__ Ag, int lda,
                                       const __half* __restrict__ Bg, int ldb,
                                       float acc[2][8][4]) {
    extern __shared__ __align__(16) char dynsmem[];
    __half* Sa = (__half*)dynsmem;                 // NSTG tiles A
    __half* Sb = Sa + NSTG * TFH;                  // NSTG tiles B
    const uint32_t suA = su32(Sa), suB = su32(Sb);
    const int tid = threadIdx.x;

    uint32_t aoff[4], boff[4];
    const __half* asrc[4]; const __half* bsrc[4];
#pragma unroll
    for (int t = 0; t < 4; t++) {
        int v = tid + t * NT;
        int r = v >> 3, q = v & 7;
        aoff[t] = (r * STRH + q * 8) * 2;
        boff[t] = aoff[t];
        asrc[t] = Ag + (size_t)r * lda + q * 8;
        bsrc[t] = Bg + (size_t)r * ldb + q * 8;
    }

#pragma unroll
    for (int mf = 0; mf < 2; mf++)
#pragma unroll
        for (int nf = 0; nf < 8; nf++)
#pragma unroll
            for (int e = 0; e < 4; e++) acc[mf][nf][e] = 0.f;

    const int lane = tid & 31, wid = tid >> 5;
    const int mw = (wid & 3) * 32, nw = (wid >> 2) * 64;
    const int lrow = ((lane >> 3) & 1) * 8 + (lane & 7);
    const int kofs = (lane >> 4) * 16;
    const uint32_t aL = (uint32_t)((mw + lrow) * 144 + kofs);
    const uint32_t bL = (uint32_t)((nw + lrow) * 144 + kofs);

    auto issue = [&](int i) {
        const int buf = i % NSTG;
        const uint32_t ab = suA + (uint32_t)(buf * TFH * 2);
        const uint32_t bb = suB + (uint32_t)(buf * TFH * 2);
        const size_t ko = (size_t)i * KCH;
#pragma unroll
        for (int t = 0; t < 4; t++) CPA16(ab + aoff[t], asrc[t] + ko);
#pragma unroll
        for (int t = 0; t < 4; t++) CPA16(bb + boff[t], bsrc[t] + ko);
        CP_COMMIT();
    };

    issue(0);
    issue(1);
#pragma unroll 1
    for (int i = 0; i < NC; i++) {
        if (i + 1 < NC) CP_WAIT(1);   // chunk i arrived (i+1 may still be in flight)
        else            CP_WAIT(0);
        __syncthreads();              // publish all threads' copies; retire compute of i-1
        if (i + 2 < NC) issue(i + 2); // safe: buf (i-1)%3 fully consumed

        const int buf = i % NSTG;
        const uint32_t Ab = suA + (uint32_t)(buf * TFH * 2) + aL;
        const uint32_t Bb = suB + (uint32_t)(buf * TFH * 2) + bL;
#pragma unroll
        for (int ks = 0; ks < 4; ks++) {
            const uint32_t ko = ks * 32;
            uint32_t a[2][4], b[8][2];
            LDSM4(a[0][0], a[0][1], a[0][2], a[0][3], Ab + ko);
            LDSM4(a[1][0], a[1][1], a[1][2], a[1][3], Ab + 16 * 144 + ko);
#pragma unroll
            for (int nf2 = 0; nf2 < 4; nf2++) {
                uint32_t q0, q1, q2, q3;
                LDSM4(q0, q1, q2, q3, Bb + nf2 * (16 * 144) + ko);
                b[2 * nf2][0] = q0; b[2 * nf2 + 1][0] = q1;
                b[2 * nf2][1] = q2; b[2 * nf2 + 1][1] = q3;
            }
#pragma unroll
            for (int mf = 0; mf < 2; mf++)
#pragma unroll
                for (int nf = 0; nf < 8; nf++) mma16(acc[mf][nf], a[mf], b[nf]);
        }
    }
    __syncthreads();   // protect smem reuse by caller epilogues
}

#define EPI_COORDS                                             \
    const int lane = threadIdx.x & 31, wid = threadIdx.x >> 5; \
    const int gp = lane >> 2, tg = lane & 3;                   \
    const int mw = (wid & 3) * 32, nw = (wid >> 2) * 64;

// ---------------- transpose kernels ------------------------------------------
__global__ void xpose_f2h(const float* __restrict__ src, __half* __restrict__ dst,
                          int R, int C)
{
    __shared__ float t[32][33];
    const int bx = blockIdx.x * 32, by = blockIdx.y * 32;
    const int tx = threadIdx.x & 31, ty = threadIdx.x >> 5;
#pragma unroll
    for (int i = 0; i < 4; i++)
        t[ty + i * 8][tx] = src[(size_t)(by + ty + i * 8) * C + bx + tx];
    __syncthreads();
#pragma unroll
    for (int i = 0; i < 4; i++)
        dst[(size_t)(bx + ty + i * 8) * R + by + tx] = __float2half_rn(t[tx][ty + i * 8]);
}

__global__ void xpose_h2h(const __half* __restrict__ src, __half* __restrict__ dst,
                          int R, int C)
{
    __shared__ __half t[32][34];
    const int bx = blockIdx.x * 32, by = blockIdx.y * 32;
    const int tx = threadIdx.x & 31, ty = threadIdx.x >> 5;
#pragma unroll
    for (int i = 0; i < 4; i++)
        t[ty + i * 8][tx] = src[(size_t)(by + ty + i * 8) * C + bx + tx];
    __syncthreads();
#pragma unroll
    for (int i = 0; i < 4; i++)
        dst[(size_t)(bx + ty + i * 8) * R + by + tx] = t[tx][ty + i * 8];
}

// ---------------- 1) projections (Q,K,V half; skip fp32) ---------------------
__global__ void __launch_bounds__(NT, 2) proj_h(
    const float* __restrict__ bq, const float* __restrict__ bk,
    const float* __restrict__ bv, const float* __restrict__ bs)
{
    const float* bias; __half* outh = nullptr; float* outf = nullptr;
    const int z = blockIdx.z;
    if      (z == 0) { bias = bq; outh = g_Qh; }
    else if (z == 1) { bias = bk; outh = g_Kh; }
    else if (z == 2) { bias = bv; outh = g_Vh; }
    else             { bias = bs; outf = g_SK; }

    const int n0 = blockIdx.y * 128, j0 = blockIdx.x * 128;
    float acc[2][8][4];
    gemm_h<LRD / KCH>(g_Xh + (size_t)n0 * LRD, LRD,
                      g_Wh[z] + (size_t)j0 * LRD, LRD, acc);

    EPI_COORDS;
#pragma unroll
    for (int mf = 0; mf < 2; mf++)
#pragma unroll
        for (int nf = 0; nf < 8; nf++) {
            int r = n0 + mw + mf * 16 + gp;
            int c = j0 + nw + nf * 8 + 2 * tg;
            float b0 = bias[c], b1 = bias[c + 1];
            float v00 = acc[mf][nf][0] + b0, v01 = acc[mf][nf][1] + b1;
            float v10 = acc[mf][nf][2] + b0, v11 = acc[mf][nf][3] + b1;
            if (outh) {
                *(half2*)&outh[(size_t)r * HRD + c]       = __floats2half2_rn(v00, v01);
                *(half2*)&outh[(size_t)(r + 8) * HRD + c] = __floats2half2_rn(v10, v11);
            } else {
                *(float2*)&outf[(size_t)r * HRD + c]       = make_float2(v00, v01);
                *(float2*)&outf[(size_t)(r + 8) * HRD + c] = make_float2(v10, v11);
            }
        }
}

// ---------------- 2) scores: half out ----------------------------------------
__global__ void __launch_bounds__(NT, 2) scores_h()
{
    const int h = blockIdx.z;
    __half* S = g_Sh + (size_t)h * NND * NND;
    const int n0 = blockIdx.y * 128, m0 = blockIdx.x * 128;

    float acc[2][8][4];
    gemm_h<CH / KCH>(g_Qh + (size_t)n0 * HRD + h * CH, HRD,
                     g_Kh + (size_t)m0 * HRD + h * CH, HRD, acc);

    const float scale = rsqrtf((float)CH);
    EPI_COORDS;
#pragma unroll
    for (int mf = 0; mf < 2; mf++)
#pragma unroll
        for (int nf = 0; nf < 8; nf++) {
            int r = n0 + mw + mf * 16 + gp;
            int c = m0 + nw + nf * 8 + 2 * tg;
            *(half2*)&S[(size_t)r * NND + c] =
                __floats2half2_rn(acc[mf][nf][0] * scale, acc[mf][nf][1] * scale);
            *(half2*)&S[(size_t)(r + 8) * NND + c] =
                __floats2half2_rn(acc[mf][nf][2] * scale, acc[mf][nf][3] * scale);
        }
}

// ---------------- 3) softmax: half row, in place ------------------------------
__global__ void softmax_kernel()
{
    __half* p = g_Sh + (size_t)blockIdx.x * NND;
    const int tid = threadIdx.x;

    float v[16];
    float mx = -INFINITY;
#pragma unroll
    for (int i = 0; i < 16; i++) { v[i] = __half2float(p[tid + i * 256]); mx = fmaxf(mx, v[i]); }

    __shared__ float red[256];
    red[tid] = mx; __syncthreads();
    for (int s = 128; s > 0; s >>= 1) {
        if (tid < s) red[tid] = fmaxf(red[tid], red[tid + s]);
        __syncthreads();
    }
    mx = red[0]; __syncthreads();

    float sum = 0.f;
#pragma unroll
    for (int i = 0; i < 16; i++) { v[i] = __expf(v[i] - mx); sum += v[i]; }

    red[tid] = sum; __syncthreads();
    for (int s = 128; s > 0; s >>= 1) {
        if (tid < s) red[tid] += red[tid + s];
        __syncthreads();
    }
    const float inv = 1.0f / red[0];
#pragma unroll
    for (int i = 0; i < 16; i++) p[tid + i * 256] = __float2half_rn(v[i] * inv);
}

// ---------------- 4) out = P @ V + skip --------------------------------------
__global__ void __launch_bounds__(NT, 2) pv_h()
{
    const int h = blockIdx.z;
    const int n0 = blockIdx.y * 128, c0 = blockIdx.x * 128;

    float acc[2][8][4];
    gemm_h<NND / KCH>(g_Sh + (size_t)h * NND * NND + (size_t)n0 * NND, NND,
                      g_VTh + (size_t)(h * CH + c0) * NND, NND, acc);

    EPI_COORDS;
#pragma unroll
    for (int mf = 0; mf < 2; mf++)
#pragma unroll
        for (int nf = 0; nf < 8; nf++) {
            int r = n0 + mw + mf * 16 + gp;
            int c = h * CH + c0 + nw + nf * 8 + 2 * tg;
            size_t g0 = (size_t)r * HRD + c, g1 = (size_t)(r + 8) * HRD + c;
            float2 s0 = *(const float2*)&g_SK[g0];
            float2 s1 = *(const float2*)&g_SK[g1];
            *(float2*)&g_O[g0] = make_float2(acc[mf][nf][0] + s0.x, acc[mf][nf][1] + s0.y);
            *(float2*)&g_O[g1] = make_float2(acc[mf][nf][2] + s1.x, acc[mf][nf][3] + s1.y);
        }
}

// ---------------- 5) per-channel stats ---------------------------------------
__global__ void stats1_kernel()
{
    const int j  = blockIdx.x * 256 + threadIdx.x;
    const int r0 = blockIdx.y * 128;
    float s = 0.f, q = 0.f;
    for (int r = 0; r < 128; r++) {
        float v = g_O[(size_t)(r0 + r) * HRD + j];
        s += v; q = fmaf(v, v, q);
    }
    g_psum[blockIdx.y * HRD + j] = s;
    g_psq [blockIdx.y * HRD + j] = q;
}

__global__ void stats2_kernel(const float* __restrict__ w, const float* __restrict__ b,
                              const float* __restrict__ ms)
{
    const int j = blockIdx.x * 256 + threadIdx.x;
    float s = 0.f, q = 0.f;
    for (int i = 0; i < 32; i++) { s += g_psum[i * HRD + j]; q += g_psq[i * HRD + j]; }
    const float invN = 1.0f / (float)NND;
    const float m    = s * invN;
    const float sc   = ms[j];
    const float var  = q * invN - 2.f * sc * m * m + sc * sc * m * m;
    const float rstd = rsqrtf(var + EPSG);
    const float wj = w[j], bj = b[j];
    const float sumc = s - (float)NND * sc * m;
    const float normsq = wj * wj * rstd * rstd * ((float)NND * var)
                       + 2.f * wj * bj * rstd * sumc
                       + (float)NND * bj * bj;
    const float inorm = rsqrtf(normsq);
    g_a[j]   = rstd * wj * inorm;
    g_c[j]   = (bj - sc * m * rstd * wj) * inorm;
    g_sum[j] = s;
}

// ---------------- 6) Gram: triangular grid + mirrored store ------------------
__global__ void __launch_bounds__(NT, 2) gram_h(float* __restrict__ out)
{
    const int t = blockIdx.x;
    int bi = (int)((sqrtf(8.f * (float)t + 1.f) - 1.f) * 0.5f);
    while ((bi + 1) * (bi + 2) / 2 <= t) bi++;
    while (bi * (bi + 1) / 2 > t) bi--;
    const int bj = t - bi * (bi + 1) / 2;
    const int i0 = bi * 128, j0 = bj * 128;

    float acc[2][8][4];
    gemm_h<NND / KCH>(g_OTh + (size_t)i0 * NND, NND,
                      g_OTh + (size_t)j0 * NND, NND, acc);

    extern __shared__ __align__(16) char dynsmem[];
    float* gs = (float*)dynsmem;

    EPI_COORDS;
#pragma unroll
    for (int mf = 0; mf < 2; mf++)
#pragma unroll
        for (int nf = 0; nf < 8; nf++) {
            int lr = mw + mf * 16 + gp;
            int lc = nw + nf * 8 + 2 * tg;
            int gi = i0 + lr, gj = j0 + lc;
            float ai0 = g_a[gi],     ci0 = g_c[gi],     Si0 = g_sum[gi];
            float ai1 = g_a[gi + 8], ci1 = g_c[gi + 8], Si1 = g_sum[gi + 8];
            float aj0 = g_a[gj],     cj0 = g_c[gj],     Sj0 = g_sum[gj];
            float aj1 = g_a[gj + 1], cj1 = g_c[gj + 1], Sj1 = g_sum[gj + 1];

            float r00 = fmaxf(ai0 * aj0 * acc[mf][nf][0] + ai0 * cj0 * Si0 + ci0 * aj0 * Sj0 + (float)NND * ci0 * cj0, 0.f);
            float r01 = fmaxf(ai0 * aj1 * acc[mf][nf][1] + ai0 * cj1 * Si0 + ci0 * aj1 * Sj1 + (float)NND * ci0 * cj1, 0.f);
            float r10 = fmaxf(ai1 * aj0 * acc[mf][nf][2] + ai1 * cj0 * Si1 + ci1 * aj0 * Sj0 + (float)NND * ci1 * cj0, 0.f);
            float r11 = fmaxf(ai1 * aj1 * acc[mf][nf][3] + ai1 * cj1 * Si1 + ci1 * aj1 * Sj1 + (float)NND * ci1 * cj1, 0.f);

            *(float2*)&out[(size_t)gi * HRD + gj]       = make_float2(r00, r01);
            *(float2*)&out[(size_t)(gi + 8) * HRD + gj] = make_float2(r10, r11);

            gs[lr * 129 + lc]           = r00;
            gs[lr * 129 + lc + 1]       = r01;
            gs[(lr + 8) * 129 + lc]     = r10;
            gs[(lr + 8) * 129 + lc + 1] = r11;
        }

    if (bi != bj) {
        __syncthreads();
        const int tid = threadIdx.x;
#pragma unroll
        for (int it = 0; it < 64; it++) {
            int v = tid + it * NT;
            int jr = v >> 7, q = v & 127;
            out[(size_t)(j0 + jr) * HRD + i0 + q] = gs[q * 129 + jr];
        }
    }
}

// ---------------- launch ------------------------------------------------------
#define DYNSMEM (NSTG * 2 * TFH * 2)   // 3 stages x 2 tiles x 18432 B = 110592 B
#define NBLK    (HRD / 128)
#define NTRI    (NBLK * (NBLK + 1) / 2)

extern "C" void kernel_launch(void* const* d_in, const int* in_sizes, int n_in,
                              void* d_out, int out_size)
{
    const float* lrx = (const float*)d_in[0];
    const float* Wq  = (const float*)d_in[1];
    const float* bq  = (const float*)d_in[2];
    const float* Wk  = (const float*)d_in[3];
    const float* bk  = (const float*)d_in[4];
    const float* Wv  = (const float*)d_in[5];
    const float* bv  = (const float*)d_in[6];
    const float* Ws  = (const float*)d_in[7];
    const float* bs  = (const float*)d_in[8];
    const float* gw  = (const float*)d_in[9];
    const float* gb  = (const float*)d_in[10];
    const float* gms = (const float*)d_in[11];

    cudaFuncSetAttribute(proj_h,   cudaFuncAttributeMaxDynamicSharedMemorySize, DYNSMEM);
    cudaFuncSetAttribute(scores_h, cudaFuncAttributeMaxDynamicSharedMemorySize, DYNSMEM);
    cudaFuncSetAttribute(pv_h,     cudaFuncAttributeMaxDynamicSharedMemorySize, DYNSMEM);
    cudaFuncSetAttribute(gram_h,   cudaFuncAttributeMaxDynamicSharedMemorySize, DYNSMEM);

    __half* whp;  cudaGetSymbolAddress((void**)&whp,  g_Wh);
    __half* xhp;  cudaGetSymbolAddress((void**)&xhp,  g_Xh);
    __half* vhp;  cudaGetSymbolAddress((void**)&vhp,  g_Vh);
    __half* vthp; cudaGetSymbolAddress((void**)&vthp, g_VTh);
    __half* othp; cudaGetSymbolAddress((void**)&othp, g_OTh);
    float*  ofp;  cudaGetSymbolAddress((void**)&ofp,  g_O);

    dim3 t(NT);
    xpose_f2h<<<dim3(NND / 32, LRD / 32), t>>>(lrx, xhp, LRD, NND);
    xpose_f2h<<<dim3(HRD / 32, LRD / 32), t>>>(Wq, whp + 0 * (size_t)HRD * LRD, LRD, HRD);
    xpose_f2h<<<dim3(HRD / 32, LRD / 32), t>>>(Wk, whp + 1 * (size_t)HRD * LRD, LRD, HRD);
    xpose_f2h<<<dim3(HRD / 32, LRD / 32), t>>>(Wv, whp + 2 * (size_t)HRD * LRD, LRD, HRD);
    xpose_f2h<<<dim3(HRD / 32, LRD / 32), t>>>(Ws, whp + 3 * (size_t)HRD * LRD, LRD, HRD);

    proj_h    <<<dim3(HRD / 128, NND / 128, 4),     t, DYNSMEM>>>(bq, bk, bv, bs);
    xpose_h2h <<<dim3(HRD / 32, NND / 32), t>>>(vhp, vthp, NND, HRD);
    scores_h  <<<dim3(NND / 128, NND / 128, HEADS), t, DYNSMEM>>>();
    softmax_kernel<<<HEADS * NND, t>>>();
    pv_h      <<<dim3(CH / 128, NND / 128, HEADS),  t, DYNSMEM>>>();
    stats1_kernel <<<dim3(HRD / 256, NND / 128), t>>>();
    stats2_kernel <<<HRD / 256, t>>>(gw, gb, gms);
    xpose_f2h <<<dim3(HRD / 32, NND / 32), t>>>(ofp, othp, NND, HRD);
    gram_h    <<<NTRI, t, DYNSMEM>>>((float*)d_out);
}

// round 10
// speedup vs baseline: 10.4162x; 1.0427x over previous
#include <cuda_runtime.h>
#include <cuda_fp16.h>
#include <math.h>
#include <stdint.h>

#define LRD   512
#define HRD   2048
#define HEADS 4
#define CH    512
#define NND   4096
#define EPSG  1e-5f
#define NT    256

#define KCH   64            // k per smem chunk (4 x k16 steps)
#define STRH  72            // smem row stride in halves (144 B)
#define TFH   (128 * STRH)  // halves per tile
#define NSTG  3             // pipeline stages

// ---------------- scratch (__device__ globals: allocation-free) --------------
__device__ __half g_Xh [NND * LRD];
__device__ __half g_Wh [4][(size_t)HRD * LRD];
__device__ __half g_Qh [NND * HRD];
__device__ __half g_Kh [NND * HRD];
__device__ __half g_VTh[(size_t)HRD * NND];          // V^T [channel][node]
__device__ float  g_SK [NND * HRD];
__device__ __half g_Sh [(size_t)HEADS * NND * NND];  // scores -> probs (in place)
__device__ __half g_OTh[(size_t)HRD * NND];          // O^T [channel][node]
__device__ float  g_psum[HRD];
__device__ float  g_psq [HRD];
__device__ float  g_sum[HRD];
__device__ float  g_a  [HRD];
__device__ float  g_c  [HRD];

// ---------------- helpers ----------------------------------------------------
__device__ __forceinline__ uint32_t su32(const void* p) {
    uint32_t a;
    asm("{ .reg .u64 t; cvta.to.shared.u64 t, %1; cvt.u32.u64 %0, t; }" : "=r"(a) : "l"(p));
    return a;
}
#define CPA16(dst, src) asm volatile("cp.async.cg.shared.global [%0], [%1], 16;" :: "r"(dst), "l"(src))
#define CP_COMMIT()     asm volatile("cp.async.commit_group;" ::: "memory")
#define CP_WAIT(n)      asm volatile("cp.async.wait_group %0;" :: "n"(n) : "memory")

#define LDSM4(r0, r1, r2, r3, addr) asm volatile( \
    "ldmatrix.sync.aligned.m8n8.x4.shared.b16 {%0,%1,%2,%3}, [%4];" \
    : "=r"(r0), "=r"(r1), "=r"(r2), "=r"(r3) : "r"(addr))

__device__ __forceinline__ void mma16(float* c, const uint32_t* a, const uint32_t* b) {
    asm volatile(
        "mma.sync.aligned.m16n8k16.row.col.f32.f16.f16.f32 "
        "{%0,%1,%2,%3}, {%4,%5,%6,%7}, {%8,%9}, {%0,%1,%2,%3};"
        : "+f"(c[0]), "+f"(c[1]), "+f"(c[2]), "+f"(c[3])
        : "r"(a[0]), "r"(a[1]), "r"(a[2]), "r"(a[3]), "r"(b[0]), "r"(b[1]));
}

// ---------------- GEMM core: C[128x128] = A(128xK) * B(128xK)^T ---------------
template<int NC>
__device__ __forceinline__ void gemm_h(const __half* __restrict__ Ag, int lda,
                                       const __half* __restrict__ Bg, int ldb,
                                       float acc[2][8][4]) {
    extern __shared__ __align__(16) char dynsmem[];
    __half* Sa = (__half*)dynsmem;
    __half* Sb = Sa + NSTG * TFH;
    const uint32_t suA = su32(Sa), suB = su32(Sb);
    const int tid = threadIdx.x;

    uint32_t aoff[4], boff[4];
    const __half* asrc[4]; const __half* bsrc[4];
#pragma unroll
    for (int t = 0; t < 4; t++) {
        int v = tid + t * NT;
        int r = v >> 3, q = v & 7;
        aoff[t] = (r * STRH + q * 8) * 2;
        boff[t] = aoff[t];
        asrc[t] = Ag + (size_t)r * lda + q * 8;
        bsrc[t] = Bg + (size_t)r * ldb + q * 8;
    }

#pragma unroll
    for (int mf = 0; mf < 2; mf++)
#pragma unroll
        for (int nf = 0; nf < 8; nf++)
#pragma unroll
            for (int e = 0; e < 4; e++) acc[mf][nf][e] = 0.f;

    const int lane = tid & 31, wid = tid >> 5;
    const int mw = (wid & 3) * 32, nw = (wid >> 2) * 64;
    const int lrow = ((lane >> 3) & 1) * 8 + (lane & 7);
    const int kofs = (lane >> 4) * 16;
    const uint32_t aL = (uint32_t)((mw + lrow) * 144 + kofs);
    const uint32_t bL = (uint32_t)((nw + lrow) * 144 + kofs);

    auto issue = [&](int i) {
        const int buf = i % NSTG;
        const uint32_t ab = suA + (uint32_t)(buf * TFH * 2);
        const uint32_t bb = suB + (uint32_t)(buf * TFH * 2);
        const size_t ko = (size_t)i * KCH;
#pragma unroll
        for (int t = 0; t < 4; t++) CPA16(ab + aoff[t], asrc[t] + ko);
#pragma unroll
        for (int t = 0; t < 4; t++) CPA16(bb + boff[t], bsrc[t] + ko);
        CP_COMMIT();
    };

    issue(0);
    issue(1);
#pragma unroll 1
    for (int i = 0; i < NC; i++) {
        if (i + 1 < NC) CP_WAIT(1);
        else            CP_WAIT(0);
        __syncthreads();
        if (i + 2 < NC) issue(i + 2);

        const int buf = i % NSTG;
        const uint32_t Ab = suA + (uint32_t)(buf * TFH * 2) + aL;
        const uint32_t Bb = suB + (uint32_t)(buf * TFH * 2) + bL;
#pragma unroll
        for (int ks = 0; ks < 4; ks++) {
            const uint32_t ko = ks * 32;
            uint32_t a[2][4], b[8][2];
            LDSM4(a[0][0], a[0][1], a[0][2], a[0][3], Ab + ko);
            LDSM4(a[1][0], a[1][1], a[1][2], a[1][3], Ab + 16 * 144 + ko);
#pragma unroll
            for (int nf2 = 0; nf2 < 4; nf2++) {
                uint32_t q0, q1, q2, q3;
                LDSM4(q0, q1, q2, q3, Bb + nf2 * (16 * 144) + ko);
                b[2 * nf2][0] = q0; b[2 * nf2 + 1][0] = q1;
                b[2 * nf2][1] = q2; b[2 * nf2 + 1][1] = q3;
            }
#pragma unroll
            for (int mf = 0; mf < 2; mf++)
#pragma unroll
                for (int nf = 0; nf < 8; nf++) mma16(acc[mf][nf], a[mf], b[nf]);
        }
    }
    __syncthreads();
}

#define EPI_COORDS                                             \
    const int lane = threadIdx.x & 31, wid = threadIdx.x >> 5; \
    const int gp = lane >> 2, tg = lane & 3;                   \
    const int mw = (wid & 3) * 32, nw = (wid >> 2) * 64;

// stage fragments (+optional add) into fp32 smem [128][129], then emit half
// transposed rows: dst[ch0+cc][n0 + q] for cc in 0..127, q in 0..127.
__device__ __forceinline__ void emit_transposed_half(
    float* gs, const float acc[2][8][4], const float* addsrc, size_t addld,
    __half* dst, int ch0, int n0)
{
    EPI_COORDS;
#pragma unroll
    for (int mf = 0; mf < 2; mf++)
#pragma unroll
        for (int nf = 0; nf < 8; nf++) {
            int lr = mw + mf * 16 + gp;
            int lc = nw + nf * 8 + 2 * tg;
            float v00 = acc[mf][nf][0], v01 = acc[mf][nf][1];
            float v10 = acc[mf][nf][2], v11 = acc[mf][nf][3];
            if (addsrc) {
                size_t a0 = (size_t)lr * addld + lc, a1 = (size_t)(lr + 8) * addld + lc;
                float2 s0 = *(const float2*)&addsrc[a0];
                float2 s1 = *(const float2*)&addsrc[a1];
                v00 += s0.x; v01 += s0.y; v10 += s1.x; v11 += s1.y;
            }
            gs[lr * 129 + lc]           = v00;
            gs[lr * 129 + lc + 1]       = v01;
            gs[(lr + 8) * 129 + lc]     = v10;
            gs[(lr + 8) * 129 + lc + 1] = v11;
        }
    __syncthreads();
    const int tid = threadIdx.x;
    const int q = tid & 127;
#pragma unroll
    for (int it = 0; it < 64; it++) {
        int cc = (tid >> 7) + it * 2;
        dst[(size_t)(ch0 + cc) * NND + n0 + q] = __float2half_rn(gs[q * 129 + cc]);
    }
}

// ---------------- 0) merged prepass transposes (fp32 -> half) -----------------
// z==0: lr_x [LRD][NND] -> g_Xh [NND][LRD]; z=1..4: W [LRD][HRD] -> g_Wh[z-1]
__global__ void xpose_all(const float* __restrict__ lrx,
                          const float* __restrict__ Wq, const float* __restrict__ Wk,
                          const float* __restrict__ Wv, const float* __restrict__ Ws)
{
    const int z = blockIdx.z;
    const float* src; __half* dst; int C;
    if (z == 0) { src = lrx; C = NND; dst = g_Xh; }
    else {
        src = (z == 1) ? Wq : (z == 2) ? Wk : (z == 3) ? Wv : Ws;
        C = HRD; dst = g_Wh[z - 1];
        if (blockIdx.x * 32 >= HRD) return;
    }
    __shared__ float t[32][33];
    const int bx = blockIdx.x * 32, by = blockIdx.y * 32;
    const int tx = threadIdx.x & 31, ty = threadIdx.x >> 5;
#pragma unroll
    for (int i = 0; i < 4; i++)
        t[ty + i * 8][tx] = src[(size_t)(by + ty + i * 8) * C + bx + tx];
    __syncthreads();
#pragma unroll
    for (int i = 0; i < 4; i++)
        dst[(size_t)(bx + ty + i * 8) * LRD + by + tx] = __float2half_rn(t[tx][ty + i * 8]);
}

// ---------------- 1) projections (Q,K half; V -> V^T; skip fp32) -------------
__global__ void __launch_bounds__(NT, 2) proj_h(
    const float* __restrict__ bq, const float* __restrict__ bk,
    const float* __restrict__ bv, const float* __restrict__ bs)
{
    const int z = blockIdx.z;
    const float* bias = (z == 0) ? bq : (z == 1) ? bk : (z == 2) ? bv : bs;

    const int n0 = blockIdx.y * 128, j0 = blockIdx.x * 128;
    float acc[2][8][4];
    gemm_h<LRD / KCH>(g_Xh + (size_t)n0 * LRD, LRD,
                      g_Wh[z] + (size_t)j0 * LRD, LRD, acc);

    EPI_COORDS;
    // add bias into acc
#pragma unroll
    for (int mf = 0; mf < 2; mf++)
#pragma unroll
        for (int nf = 0; nf < 8; nf++) {
            int c = j0 + nw + nf * 8 + 2 * tg;
            float b0 = bias[c], b1 = bias[c + 1];
            acc[mf][nf][0] += b0; acc[mf][nf][1] += b1;
            acc[mf][nf][2] += b0; acc[mf][nf][3] += b1;
        }

    if (z == 2) {   // V: emit transposed half directly
        extern __shared__ __align__(16) char dynsmem[];
        emit_transposed_half((float*)dynsmem, acc, nullptr, 0, g_VTh, j0, n0);
        return;
    }

    __half* outh = (z == 0) ? g_Qh : (z == 1) ? g_Kh : nullptr;
#pragma unroll
    for (int mf = 0; mf < 2; mf++)
#pragma unroll
        for (int nf = 0; nf < 8; nf++) {
            int r = n0 + mw + mf * 16 + gp;
            int c = j0 + nw + nf * 8 + 2 * tg;
            if (outh) {
                *(half2*)&outh[(size_t)r * HRD + c] =
                    __floats2half2_rn(acc[mf][nf][0], acc[mf][nf][1]);
                *(half2*)&outh[(size_t)(r + 8) * HRD + c] =
                    __floats2half2_rn(acc[mf][nf][2], acc[mf][nf][3]);
            } else {
                *(float2*)&g_SK[(size_t)r * HRD + c] =
                    make_float2(acc[mf][nf][0], acc[mf][nf][1]);
                *(float2*)&g_SK[(size_t)(r + 8) * HRD + c] =
                    make_float2(acc[mf][nf][2], acc[mf][nf][3]);
            }
        }
}

// ---------------- 2) scores: half out ----------------------------------------
__global__ void __launch_bounds__(NT, 2) scores_h()
{
    const int h = blockIdx.z;
    __half* S = g_Sh + (size_t)h * NND * NND;
    const int n0 = blockIdx.y * 128, m0 = blockIdx.x * 128;

    float acc[2][8][4];
    gemm_h<CH / KCH>(g_Qh + (size_t)n0 * HRD + h * CH, HRD,
                     g_Kh + (size_t)m0 * HRD + h * CH, HRD, acc);

    const float scale = rsqrtf((float)CH);
    EPI_COORDS;
#pragma unroll
    for (int mf = 0; mf < 2; mf++)
#pragma unroll
        for (int nf = 0; nf < 8; nf++) {
            int r = n0 + mw + mf * 16 + gp;
            int c = m0 + nw + nf * 8 + 2 * tg;
            *(half2*)&S[(size_t)r * NND + c] =
                __floats2half2_rn(acc[mf][nf][0] * scale, acc[mf][nf][1] * scale);
            *(half2*)&S[(size_t)(r + 8) * NND + c] =
                __floats2half2_rn(acc[mf][nf][2] * scale, acc[mf][nf][3] * scale);
        }
}

// ---------------- 3) softmax: vectorized half row, in place ------------------
__global__ void softmax_kernel()
{
    uint4* p = (uint4*)(g_Sh + (size_t)blockIdx.x * NND);
    const int tid = threadIdx.x;

    uint4 u0 = p[tid * 2], u1 = p[tid * 2 + 1];
    float v[16];
    {
        const __half2* h0 = (const __half2*)&u0;
        const __half2* h1 = (const __half2*)&u1;
#pragma unroll
        for (int i = 0; i < 4; i++) {
            float2 f0 = __half22float2(h0[i]);
            float2 f1 = __half22float2(h1[i]);
            v[2 * i] = f0.x; v[2 * i + 1] = f0.y;
            v[8 + 2 * i] = f1.x; v[8 + 2 * i + 1] = f1.y;
        }
    }
    float mx = -INFINITY;
#pragma unroll
    for (int i = 0; i < 16; i++) mx = fmaxf(mx, v[i]);

    __shared__ float red[256];
    red[tid] = mx; __syncthreads();
    for (int s = 128; s > 0; s >>= 1) {
        if (tid < s) red[tid] = fmaxf(red[tid], red[tid + s]);
        __syncthreads();
    }
    mx = red[0]; __syncthreads();

    float sum = 0.f;
#pragma unroll
    for (int i = 0; i < 16; i++) { v[i] = __expf(v[i] - mx); sum += v[i]; }

    red[tid] = sum; __syncthreads();
    for (int s = 128; s > 0; s >>= 1) {
        if (tid < s) red[tid] += red[tid + s];
        __syncthreads();
    }
    const float inv = 1.0f / red[0];

    {
        __half2* h0 = (__half2*)&u0;
        __half2* h1 = (__half2*)&u1;
#pragma unroll
        for (int i = 0; i < 4; i++) {
            h0[i] = __floats2half2_rn(v[2 * i] * inv, v[2 * i + 1] * inv);
            h1[i] = __floats2half2_rn(v[8 + 2 * i] * inv, v[8 + 2 * i + 1] * inv);
        }
    }
    p[tid * 2] = u0; p[tid * 2 + 1] = u1;
}

// ---------------- 4) out = P @ V + skip -> O^T half directly ------------------
__global__ void __launch_bounds__(NT, 2) pv_h()
{
    const int h = blockIdx.z;
    const int n0 = blockIdx.y * 128, c0 = blockIdx.x * 128;

    float acc[2][8][4];
    gemm_h<NND / KCH>(g_Sh + (size_t)h * NND * NND + (size_t)n0 * NND, NND,
                      g_VTh + (size_t)(h * CH + c0) * NND, NND, acc);

    extern __shared__ __align__(16) char dynsmem[];
    emit_transposed_half((float*)dynsmem, acc,
                         g_SK + (size_t)n0 * HRD + h * CH + c0, HRD,
                         g_OTh, h * CH + c0, n0);
}

// ---------------- 5) per-channel stats from O^T (one warp / channel) ---------
__global__ void stats1_kernel()
{
    const int wid = threadIdx.x >> 5, lane = threadIdx.x & 31;
    const int ch = blockIdx.x * 8 + wid;
    const __half2* row = (const __half2*)(g_OTh + (size_t)ch * NND);
    float s = 0.f, q = 0.f;
#pragma unroll 8
    for (int i = 0; i < NND / 64; i++) {
        float2 f = __half22float2(row[lane + i * 32]);
        s += f.x + f.y;
        q = fmaf(f.x, f.x, q); q = fmaf(f.y, f.y, q);
    }
#pragma unroll
    for (int off = 16; off > 0; off >>= 1) {
        s += __shfl_down_sync(0xFFFFFFFF, s, off);
        q += __shfl_down_sync(0xFFFFFFFF, q, off);
    }
    if (lane == 0) { g_psum[ch] = s; g_psq[ch] = q; }
}

__global__ void stats2_kernel(const float* __restrict__ w, const float* __restrict__ b,
                              const float* __restrict__ ms)
{
    const int j = blockIdx.x * 256 + threadIdx.x;
    const float s = g_psum[j], q = g_psq[j];
    const float invN = 1.0f / (float)NND;
    const float m    = s * invN;
    const float sc   = ms[j];
    const float var  = q * invN - 2.f * sc * m * m + sc * sc * m * m;
    const float rstd = rsqrtf(var + EPSG);
    const float wj = w[j], bj = b[j];
    const float sumc = s - (float)NND * sc * m;
    const float normsq = wj * wj * rstd * rstd * ((float)NND * var)
                       + 2.f * wj * bj * rstd * sumc
                       + (float)NND * bj * bj;
    const float inorm = rsqrtf(normsq);
    g_a[j]   = rstd * wj * inorm;
    g_c[j]   = (bj - sc * m * rstd * wj) * inorm;
    g_sum[j] = s;
}

// ---------------- 6) Gram: triangular grid + mirrored store ------------------
__global__ void __launch_bounds__(NT, 2) gram_h(float* __restrict__ out)
{
    const int t = blockIdx.x;
    int bi = (int)((sqrtf(8.f * (float)t + 1.f) - 1.f) * 0.5f);
    while ((bi + 1) * (bi + 2) / 2 <= t) bi++;
    while (bi * (bi + 1) / 2 > t) bi--;
    const int bj = t - bi * (bi + 1) / 2;
    const int i0 = bi * 128, j0 = bj * 128;

    float acc[2][8][4];
    gemm_h<NND / KCH>(g_OTh + (size_t)i0 * NND, NND,
                      g_OTh + (size_t)j0 * NND, NND, acc);

    extern __shared__ __align__(16) char dynsmem[];
    float* gs = (float*)dynsmem;

    EPI_COORDS;
#pragma unroll
    for (int mf = 0; mf < 2; mf++)
#pragma unroll
        for (int nf = 0; nf < 8; nf++) {
            int lr = mw + mf * 16 + gp;
            int lc = nw + nf * 8 + 2 * tg;
            int gi = i0 + lr, gj = j0 + lc;
            float ai0 = g_a[gi],     ci0 = g_c[gi],     Si0 = g_sum[gi];
            float ai1 = g_a[gi + 8], ci1 = g_c[gi + 8], Si1 = g_sum[gi + 8];
            float aj0 = g_a[gj],     cj0 = g_c[gj],     Sj0 = g_sum[gj];
            float aj1 = g_a[gj + 1], cj1 = g_c[gj + 1], Sj1 = g_sum[gj + 1];

            float r00 = fmaxf(ai0 * aj0 * acc[mf][nf][0] + ai0 * cj0 * Si0 + ci0 * aj0 * Sj0 + (float)NND * ci0 * cj0, 0.f);
            float r01 = fmaxf(ai0 * aj1 * acc[mf][nf][1] + ai0 * cj1 * Si0 + ci0 * aj1 * Sj1 + (float)NND * ci0 * cj1, 0.f);
            float r10 = fmaxf(ai1 * aj0 * acc[mf][nf][2] + ai1 * cj0 * Si1 + ci1 * aj0 * Sj0 + (float)NND * ci1 * cj0, 0.f);
            float r11 = fmaxf(ai1 * aj1 * acc[mf][nf][3] + ai1 * cj1 * Si1 + ci1 * aj1 * Sj1 + (float)NND * ci1 * cj1, 0.f);

            *(float2*)&out[(size_t)gi * HRD + gj]       = make_float2(r00, r01);
            *(float2*)&out[(size_t)(gi + 8) * HRD + gj] = make_float2(r10, r11);

            gs[lr * 129 + lc]           = r00;
            gs[lr * 129 + lc + 1]       = r01;
            gs[(lr + 8) * 129 + lc]     = r10;
            gs[(lr + 8) * 129 + lc + 1] = r11;
        }

    if (bi != bj) {
        __syncthreads();
        const int tid = threadIdx.x;
#pragma unroll
        for (int it = 0; it < 64; it++) {
            int v = tid + it * NT;
            int jr = v >> 7, q = v & 127;
            out[(size_t)(j0 + jr) * HRD + i0 + q] = gs[q * 129 + jr];
        }
    }
}

// ---------------- launch ------------------------------------------------------
#define DYNSMEM (NSTG * 2 * TFH * 2)   // 110592 B (covers 128x129 fp32 staging)
#define NBLK    (HRD / 128)
#define NTRI    (NBLK * (NBLK + 1) / 2)

extern "C" void kernel_launch(void* const* d_in, const int* in_sizes, int n_in,
                              void* d_out, int out_size)
{
    const float* lrx = (const float*)d_in[0];
    const float* Wq  = (const float*)d_in[1];
    const float* bq  = (const float*)d_in[2];
    const float* Wk  = (const float*)d_in[3];
    const float* bk  = (const float*)d_in[4];
    const float* Wv  = (const float*)d_in[5];
    const float* bv  = (const float*)d_in[6];
    const float* Ws  = (const float*)d_in[7];
    const float* bs  = (const float*)d_in[8];
    const float* gw  = (const float*)d_in[9];
    const float* gb  = (const float*)d_in[10];
    const float* gms = (const float*)d_in[11];

    cudaFuncSetAttribute(proj_h,   cudaFuncAttributeMaxDynamicSharedMemorySize, DYNSMEM);
    cudaFuncSetAttribute(scores_h, cudaFuncAttributeMaxDynamicSharedMemorySize, DYNSMEM);
    cudaFuncSetAttribute(pv_h,     cudaFuncAttributeMaxDynamicSharedMemorySize, DYNSMEM);
    cudaFuncSetAttribute(gram_h,   cudaFuncAttributeMaxDynamicSharedMemorySize, DYNSMEM);

    dim3 t(NT);
    xpose_all<<<dim3(NND / 32, LRD / 32, 5), t>>>(lrx, Wq, Wk, Wv, Ws);
    proj_h    <<<dim3(HRD / 128, NND / 128, 4),     t, DYNSMEM>>>(bq, bk, bv, bs);
    scores_h  <<<dim3(NND / 128, NND / 128, HEADS), t, DYNSMEM>>>();
    softmax_kernel<<<HEADS * NND, t>>>();
    pv_h      <<<dim3(CH / 128, NND / 128, HEADS),  t, DYNSMEM>>>();
    stats1_kernel <<<HRD / 8, t>>>();
    stats2_kernel <<<HRD / 256, t>>>(gw, gb, gms);
    gram_h    <<<NTRI, t, DYNSMEM>>>((float*)d_out);
}